// round 1
// baseline (speedup 1.0000x reference)
#include <cuda_runtime.h>

#define HID   2048
#define MROWS 4096   // B*S
#define NHEAD 16
#define HDIM  128
#define SEQ   2048
#define BH    32     // B*NHEAD

// Scratch (no allocations allowed): ~134 MB total
__device__ float g_Qt[BH * HDIM * SEQ];    // [bh][d][s]  (d-major for attention loads)
__device__ float g_Kt[BH * HDIM * SEQ];    // [bh][d][s]
__device__ float g_V [BH * SEQ * HDIM];    // [bh][s][d]
__device__ float g_attn[(size_t)MROWS * HID]; // [B*S][nh*hd]

// ---------------------------------------------------------------------------
// SGEMM: C[m,n] = sum_k A[m,k] * W[n,k] + bias[n]
// M=4096, N=K=2048. 128x128 tile, BK=8, 256 threads, 8x8 per thread.
// mode 0: plain row-major out[m*HID + n]
// mode 1: Q/K transposed store: out[(bh*128 + d)*2048 + s]
// mode 2: V store: out[(bh*2048 + s)*128 + d]
// ---------------------------------------------------------------------------
__global__ __launch_bounds__(256)
void sgemm_kernel(const float* __restrict__ A,
                  const float* __restrict__ W,
                  const float* __restrict__ bias,
                  float* __restrict__ out,
                  int mode)
{
    __shared__ float As[8][128];
    __shared__ float Ws[8][128];

    const int t  = threadIdx.x;
    const int m0 = blockIdx.y * 128;
    const int n0 = blockIdx.x * 128;
    const int tm = (t >> 4) * 8;
    const int tn = (t & 15) * 8;

    float acc[8][8];
#pragma unroll
    for (int i = 0; i < 8; i++)
#pragma unroll
        for (int j = 0; j < 8; j++) acc[i][j] = 0.f;

    const int lr = t >> 1;        // 0..127
    const int lk = (t & 1) * 4;   // 0 or 4
    const float* Ap = A + (size_t)(m0 + lr) * HID + lk;
    const float* Wp = W + (size_t)(n0 + lr) * HID + lk;

    for (int k0 = 0; k0 < HID; k0 += 8) {
        float4 av = *(const float4*)(Ap + k0);
        float4 wv = *(const float4*)(Wp + k0);
        __syncthreads();
        As[lk + 0][lr] = av.x; As[lk + 1][lr] = av.y;
        As[lk + 2][lr] = av.z; As[lk + 3][lr] = av.w;
        Ws[lk + 0][lr] = wv.x; Ws[lk + 1][lr] = wv.y;
        Ws[lk + 2][lr] = wv.z; Ws[lk + 3][lr] = wv.w;
        __syncthreads();
#pragma unroll
        for (int kk = 0; kk < 8; kk++) {
            float a[8], b[8];
            *(float4*)&a[0] = *(const float4*)&As[kk][tm];
            *(float4*)&a[4] = *(const float4*)&As[kk][tm + 4];
            *(float4*)&b[0] = *(const float4*)&Ws[kk][tn];
            *(float4*)&b[4] = *(const float4*)&Ws[kk][tn + 4];
#pragma unroll
            for (int i = 0; i < 8; i++)
#pragma unroll
                for (int j = 0; j < 8; j++)
                    acc[i][j] += a[i] * b[j];
        }
    }

    float bv[8];
#pragma unroll
    for (int j = 0; j < 8; j++) bv[j] = bias[n0 + tn + j];

    if (mode == 0) {
#pragma unroll
        for (int i = 0; i < 8; i++) {
            int m = m0 + tm + i;
            float4 c0, c1;
            c0.x = acc[i][0] + bv[0]; c0.y = acc[i][1] + bv[1];
            c0.z = acc[i][2] + bv[2]; c0.w = acc[i][3] + bv[3];
            c1.x = acc[i][4] + bv[4]; c1.y = acc[i][5] + bv[5];
            c1.z = acc[i][6] + bv[6]; c1.w = acc[i][7] + bv[7];
            *(float4*)&out[(size_t)m * HID + n0 + tn]     = c0;
            *(float4*)&out[(size_t)m * HID + n0 + tn + 4] = c1;
        }
    } else if (mode == 1) {
        // out[((b*16 + h)*128 + d)*2048 + s]
#pragma unroll
        for (int i = 0; i < 8; i++) {
            int m = m0 + tm + i;
            int b = m >> 11, s = m & 2047;
#pragma unroll
            for (int j = 0; j < 8; j++) {
                int n = n0 + tn + j;
                int h = n >> 7, d = n & 127;
                out[(size_t)((b * NHEAD + h) * HDIM + d) * SEQ + s] = acc[i][j] + bv[j];
            }
        }
    } else {
        // out[((b*16 + h)*2048 + s)*128 + d]
#pragma unroll
        for (int i = 0; i < 8; i++) {
            int m = m0 + tm + i;
            int b = m >> 11, s = m & 2047;
            int n = n0 + tn;
            int h = n >> 7, d = n & 127;
            float4 c0, c1;
            c0.x = acc[i][0] + bv[0]; c0.y = acc[i][1] + bv[1];
            c0.z = acc[i][2] + bv[2]; c0.w = acc[i][3] + bv[3];
            c1.x = acc[i][4] + bv[4]; c1.y = acc[i][5] + bv[5];
            c1.z = acc[i][6] + bv[6]; c1.w = acc[i][7] + bv[7];
            float* dst = &out[(size_t)((b * NHEAD + h) * SEQ + s) * HDIM + d];
            *(float4*)dst       = c0;
            *(float4*)(dst + 4) = c1;
        }
    }
}

// ---------------------------------------------------------------------------
// Flash attention (causal). One block = 64 query rows of one (b,h).
// 256 threads as 16x16 (tx = keys/hd cols, ty = query rows).
// Shared: Qs [128][64] (d-major, scaled), KV union (K:[128][64], V:[64][132]),
//         Ps [64 keys][65] (padded).
// ---------------------------------------------------------------------------
#define SM_Q  (128 * 64)
#define SM_KV (64 * 132)
#define SM_P  (64 * 65)
#define SMEM_FLOATS (SM_Q + SM_KV + SM_P)

__global__ __launch_bounds__(256)
void attn_kernel()
{
    extern __shared__ float sm[];
    float* Qs = sm;
    float* KV = sm + SM_Q;
    float* Ps = sm + SM_Q + SM_KV;

    const int t  = threadIdx.x;
    const int tx = t & 15, ty = t >> 4;
    const int qb = blockIdx.x, bh = blockIdx.y;
    const int q0 = qb * 64;
    const float scale = 0.08838834764831845f; // 1/sqrt(128)

    const float* Qg = g_Qt + (size_t)bh * HDIM * SEQ;
    const float* Kg = g_Kt + (size_t)bh * HDIM * SEQ;
    const float* Vg = g_V  + (size_t)bh * SEQ * HDIM;

    // Load Q tile (pre-scaled): Qs[d*64 + s]
#pragma unroll
    for (int it = 0; it < 8; it++) {
        int idx = t + it * 256;
        int d = idx >> 4, s4 = (idx & 15) * 4;
        float4 v = *(const float4*)&Qg[(size_t)d * SEQ + q0 + s4];
        v.x *= scale; v.y *= scale; v.z *= scale; v.w *= scale;
        *(float4*)&Qs[d * 64 + s4] = v;
    }

    float m_r[4], l_r[4], O[4][8];
#pragma unroll
    for (int i = 0; i < 4; i++) {
        m_r[i] = -1e30f; l_r[i] = 0.f;
#pragma unroll
        for (int j = 0; j < 8; j++) O[i][j] = 0.f;
    }

    for (int kb = 0; kb <= qb; kb++) {
        const int k0 = kb * 64;
        __syncthreads();
        // Load K tile: KV[d*64 + c]
#pragma unroll
        for (int it = 0; it < 8; it++) {
            int idx = t + it * 256;
            int d = idx >> 4, c4 = (idx & 15) * 4;
            *(float4*)&KV[d * 64 + c4] =
                *(const float4*)&Kg[(size_t)d * SEQ + k0 + c4];
        }
        __syncthreads();

        // S = Q·K^T (already scaled via Q)
        float S[4][4];
#pragma unroll
        for (int i = 0; i < 4; i++)
#pragma unroll
            for (int j = 0; j < 4; j++) S[i][j] = 0.f;

        for (int d = 0; d < 128; d++) {
            float a[4], b[4];
            *(float4*)a = *(const float4*)&Qs[d * 64 + 4 * ty];
            *(float4*)b = *(const float4*)&KV[d * 64 + 4 * tx];
#pragma unroll
            for (int i = 0; i < 4; i++)
#pragma unroll
                for (int j = 0; j < 4; j++)
                    S[i][j] += a[i] * b[j];
        }

        if (kb == qb) {
#pragma unroll
            for (int i = 0; i < 4; i++)
#pragma unroll
                for (int j = 0; j < 4; j++)
                    if (4 * tx + j > 4 * ty + i) S[i][j] = -1e30f;
        }

        // Online softmax per row
#pragma unroll
        for (int i = 0; i < 4; i++) {
            float rmax = fmaxf(fmaxf(S[i][0], S[i][1]), fmaxf(S[i][2], S[i][3]));
#pragma unroll
            for (int off = 1; off < 16; off <<= 1)
                rmax = fmaxf(rmax, __shfl_xor_sync(0xffffffffu, rmax, off));
            float mnew = fmaxf(m_r[i], rmax);
            float corr = __expf(m_r[i] - mnew);
            float p[4], rsum = 0.f;
#pragma unroll
            for (int j = 0; j < 4; j++) {
                p[j] = __expf(S[i][j] - mnew);
                rsum += p[j];
            }
#pragma unroll
            for (int off = 1; off < 16; off <<= 1)
                rsum += __shfl_xor_sync(0xffffffffu, rsum, off);
            l_r[i] = l_r[i] * corr + rsum;
            m_r[i] = mnew;
#pragma unroll
            for (int j = 0; j < 8; j++) O[i][j] *= corr;
#pragma unroll
            for (int j = 0; j < 4; j++)
                Ps[(4 * tx + j) * 65 + 4 * ty + i] = p[j];
        }

        __syncthreads();
        // Load V tile into same buffer: KV[k*132 + d]
#pragma unroll
        for (int it = 0; it < 8; it++) {
            int idx = t + it * 256;
            int k = idx >> 5, d4 = (idx & 31) * 4;
            *(float4*)&KV[k * 132 + d4] =
                *(const float4*)&Vg[(size_t)(k0 + k) * HDIM + d4];
        }
        __syncthreads();

        // O += P·V   (thread covers rows 4ty+i, cols 8tx+j)
        for (int k = 0; k < 64; k++) {
            float p0 = Ps[k * 65 + 4 * ty + 0];
            float p1 = Ps[k * 65 + 4 * ty + 1];
            float p2 = Ps[k * 65 + 4 * ty + 2];
            float p3 = Ps[k * 65 + 4 * ty + 3];
            float v[8];
            *(float4*)&v[0] = *(const float4*)&KV[k * 132 + 8 * tx];
            *(float4*)&v[4] = *(const float4*)&KV[k * 132 + 8 * tx + 4];
#pragma unroll
            for (int j = 0; j < 8; j++) {
                O[0][j] += p0 * v[j];
                O[1][j] += p1 * v[j];
                O[2][j] += p2 * v[j];
                O[3][j] += p3 * v[j];
            }
        }
    }

    // Normalize and write: g_attn[((b*2048 + row)*16 + h)*128 + col]
    const int b = bh >> 4, h = bh & 15;
#pragma unroll
    for (int i = 0; i < 4; i++) {
        float inv = 1.f / l_r[i];
        int row = q0 + 4 * ty + i;
        float* dst = &g_attn[(size_t)((b * SEQ + row) * NHEAD + h) * HDIM + 8 * tx];
        float4 o0, o1;
        o0.x = O[i][0] * inv; o0.y = O[i][1] * inv;
        o0.z = O[i][2] * inv; o0.w = O[i][3] * inv;
        o1.x = O[i][4] * inv; o1.y = O[i][5] * inv;
        o1.z = O[i][6] * inv; o1.w = O[i][7] * inv;
        *(float4*)dst       = o0;
        *(float4*)(dst + 4) = o1;
    }
}

// ---------------------------------------------------------------------------
extern "C" void kernel_launch(void* const* d_in, const int* in_sizes, int n_in,
                              void* d_out, int out_size)
{
    const float* x  = (const float*)d_in[0];
    const float* Wq = (const float*)d_in[1];
    const float* bq = (const float*)d_in[2];
    const float* Wk = (const float*)d_in[3];
    const float* bk = (const float*)d_in[4];
    const float* Wv = (const float*)d_in[5];
    const float* bv = (const float*)d_in[6];
    const float* Wo = (const float*)d_in[7];
    const float* bo = (const float*)d_in[8];
    float* out = (float*)d_out;

    float *qt, *kt, *vv, *attn;
    cudaGetSymbolAddress((void**)&qt,   g_Qt);
    cudaGetSymbolAddress((void**)&kt,   g_Kt);
    cudaGetSymbolAddress((void**)&vv,   g_V);
    cudaGetSymbolAddress((void**)&attn, g_attn);

    const size_t smem = SMEM_FLOATS * sizeof(float); // 83,200 B
    cudaFuncSetAttribute(attn_kernel,
                         cudaFuncAttributeMaxDynamicSharedMemorySize, (int)smem);

    dim3 gemm_grid(HID / 128, MROWS / 128); // (16, 32)
    sgemm_kernel<<<gemm_grid, 256>>>(x, Wq, bq, qt, 1);
    sgemm_kernel<<<gemm_grid, 256>>>(x, Wk, bk, kt, 1);
    sgemm_kernel<<<gemm_grid, 256>>>(x, Wv, bv, vv, 2);
    attn_kernel<<<dim3(SEQ / 64, BH), 256, smem>>>();
    sgemm_kernel<<<gemm_grid, 256>>>(attn, Wo, bo, out, 0);
}

// round 2
// speedup vs baseline: 2.2865x; 2.2865x over previous
#include <cuda_runtime.h>
#include <cstdint>

#define HID   2048
#define MROWS 4096   // B*S
#define NHEAD 16
#define HDIM  128
#define SEQ   2048
#define BH    32     // B*NHEAD

// Scratch (no allocations allowed)
__device__ float g_Qt[BH * HDIM * SEQ];       // [bh][d][s]
__device__ float g_Kt[BH * HDIM * SEQ];       // [bh][d][s]
__device__ float g_V [BH * SEQ * HDIM];       // [bh][s][d]
__device__ float g_attn[(size_t)MROWS * HID]; // [B*S][nh*hd]

// ---------------------------------------------------------------------------
// tf32 tensor-core GEMM: C[m,n] = sum_k A[m,k]*W[n,k] + bias[n]
// Block 128x128, BK=32, 256 thr = 8 warps (4 m-slices x 2 n-slices),
// warp tile 32m x 64n = 2 x 8 mma(m16n8k8) tiles.
// cp.async double-buffered smem, XOR-swizzled rows (32 floats/row, chunk^row).
// modes: 0 = row-major out[m][n]; 1 = Q/K transposed [(bh*128+d)*2048+s];
//        2 = V [(bh*2048+s)*128+d]
// ---------------------------------------------------------------------------
#define BK 32
#define NKT (HID / BK)   // 64

__device__ __forceinline__ void cp_async16(void* smem_dst, const void* gmem_src) {
    uint32_t s = (uint32_t)__cvta_generic_to_shared(smem_dst);
    asm volatile("cp.async.cg.shared.global [%0], [%1], 16;\n" :: "r"(s), "l"(gmem_src));
}
__device__ __forceinline__ uint32_t f2tf32(float f) {
    uint32_t u;
    asm("cvt.rna.tf32.f32 %0, %1;" : "=r"(u) : "f"(f));
    return u;
}
__device__ __forceinline__ void mma_tf32(float* d, const uint32_t* a, const uint32_t* b) {
    asm volatile(
        "mma.sync.aligned.m16n8k8.row.col.f32.tf32.tf32.f32 "
        "{%0,%1,%2,%3}, {%4,%5,%6,%7}, {%8,%9}, {%0,%1,%2,%3};"
        : "+f"(d[0]), "+f"(d[1]), "+f"(d[2]), "+f"(d[3])
        : "r"(a[0]), "r"(a[1]), "r"(a[2]), "r"(a[3]), "r"(b[0]), "r"(b[1]));
}

// smem: 2 buffers x (A 4096 + W 4096) floats = 64KB
#define BUF_FLOATS 8192

__global__ __launch_bounds__(256, 2)
void gemm_tf32_kernel(const float* __restrict__ A,
                      const float* __restrict__ W,
                      const float* __restrict__ bias,
                      float* __restrict__ out,
                      int mode)
{
    extern __shared__ float sm[];
    const int t    = threadIdx.x;
    const int lane = t & 31;
    const int wid  = t >> 5;
    const int wm   = wid & 3;   // 4 m-slices of 32
    const int wn   = wid >> 2;  // 2 n-slices of 64
    const int m0   = blockIdx.y * 128;
    const int n0   = blockIdx.x * 128;

    const int r = lane >> 2;   // 0..7
    const int c = lane & 3;    // 0..3

    // load indices for cp.async: 1024 16B-chunks per tile, 4 per thread
    const int lrow = t >> 1;          // not used; chunk mapping below
    (void)lrow;

    float acc[2][8][4];
#pragma unroll
    for (int i = 0; i < 2; i++)
#pragma unroll
        for (int j = 0; j < 8; j++)
#pragma unroll
            for (int e = 0; e < 4; e++) acc[i][j][e] = 0.f;

    auto issue_tile = [&](int kt, int buf) {
        float* As = sm + buf * BUF_FLOATS;
        float* Ws = As + 4096;
        const int k0 = kt * BK;
#pragma unroll
        for (int i = 0; i < 4; i++) {
            int id  = t + i * 256;       // 0..1023
            int row = id >> 3;           // 0..127
            int ck  = id & 7;            // 0..7
            int swk = (ck ^ (row & 7)) << 2;
            cp_async16(As + row * 32 + swk,
                       A + (size_t)(m0 + row) * HID + k0 + ck * 4);
            cp_async16(Ws + row * 32 + swk,
                       W + (size_t)(n0 + row) * HID + k0 + ck * 4);
        }
        asm volatile("cp.async.commit_group;\n");
    };

    issue_tile(0, 0);

    for (int kt = 0; kt < NKT; kt++) {
        if (kt + 1 < NKT) {
            issue_tile(kt + 1, (kt + 1) & 1);
            asm volatile("cp.async.wait_group 1;\n");
        } else {
            asm volatile("cp.async.wait_group 0;\n");
        }
        __syncthreads();

        const float* As = sm + (kt & 1) * BUF_FLOATS;
        const float* Ws = As + 4096;

#pragma unroll
        for (int ks = 0; ks < 4; ks++) {
            uint32_t af[2][4];
#pragma unroll
            for (int i = 0; i < 2; i++) {
                int mrow = wm * 32 + i * 16 + r;
                int ch0 = ((2 * ks) ^ r) << 2;
                int ch1 = ((2 * ks + 1) ^ r) << 2;
                af[i][0] = f2tf32(As[mrow * 32 + ch0 + c]);
                af[i][1] = f2tf32(As[(mrow + 8) * 32 + ch0 + c]);
                af[i][2] = f2tf32(As[mrow * 32 + ch1 + c]);
                af[i][3] = f2tf32(As[(mrow + 8) * 32 + ch1 + c]);
            }
            uint32_t bf[8][2];
#pragma unroll
            for (int j = 0; j < 8; j++) {
                int nrow = wn * 64 + j * 8 + r;
                int ch0 = ((2 * ks) ^ r) << 2;
                int ch1 = ((2 * ks + 1) ^ r) << 2;
                bf[j][0] = f2tf32(Ws[nrow * 32 + ch0 + c]);
                bf[j][1] = f2tf32(Ws[nrow * 32 + ch1 + c]);
            }
#pragma unroll
            for (int i = 0; i < 2; i++)
#pragma unroll
                for (int j = 0; j < 8; j++)
                    mma_tf32(acc[i][j], af[i], bf[j]);
        }
        __syncthreads();
    }

    // Epilogue. Thread owns: rows r0 = m0+wm*32+i*16+r, r1 = r0+8;
    // cols nb = n0+wn*64+j*8+2c (+0/+1).
#pragma unroll
    for (int i = 0; i < 2; i++) {
        int r0 = m0 + wm * 32 + i * 16 + r;
        int r1 = r0 + 8;
#pragma unroll
        for (int j = 0; j < 8; j++) {
            int nb = n0 + wn * 64 + j * 8 + 2 * c;
            float b0 = bias[nb], b1 = bias[nb + 1];
            float d00 = acc[i][j][0] + b0, d01 = acc[i][j][1] + b1;
            float d10 = acc[i][j][2] + b0, d11 = acc[i][j][3] + b1;
            if (mode == 0) {
                *(float2*)&out[(size_t)r0 * HID + nb] = make_float2(d00, d01);
                *(float2*)&out[(size_t)r1 * HID + nb] = make_float2(d10, d11);
            } else if (mode == 1) {
                int h = nb >> 7, d = nb & 127;
                int b_0 = r0 >> 11, s_0 = r0 & 2047;
                int b_1 = r1 >> 11, s_1 = r1 & 2047;
                size_t base0 = (size_t)((b_0 * NHEAD + h) * HDIM + d) * SEQ;
                size_t base1 = (size_t)((b_1 * NHEAD + h) * HDIM + d) * SEQ;
                out[base0 + s_0]       = d00;
                out[base0 + SEQ + s_0] = d01;
                out[base1 + s_1]       = d10;
                out[base1 + SEQ + s_1] = d11;
            } else {
                int h = nb >> 7, d = nb & 127;
                int b_0 = r0 >> 11, s_0 = r0 & 2047;
                int b_1 = r1 >> 11, s_1 = r1 & 2047;
                *(float2*)&out[(size_t)((b_0 * NHEAD + h) * SEQ + s_0) * HDIM + d] =
                    make_float2(d00, d01);
                *(float2*)&out[(size_t)((b_1 * NHEAD + h) * SEQ + s_1) * HDIM + d] =
                    make_float2(d10, d11);
            }
        }
    }
}

// ---------------------------------------------------------------------------
// Flash attention (causal), fp32 SIMT — unchanged from round 0.
// ---------------------------------------------------------------------------
#define SM_Q  (128 * 64)
#define SM_KV (64 * 132)
#define SM_P  (64 * 65)
#define SMEM_FLOATS (SM_Q + SM_KV + SM_P)

__global__ __launch_bounds__(256)
void attn_kernel()
{
    extern __shared__ float sm[];
    float* Qs = sm;
    float* KV = sm + SM_Q;
    float* Ps = sm + SM_Q + SM_KV;

    const int t  = threadIdx.x;
    const int tx = t & 15, ty = t >> 4;
    const int qb = blockIdx.x, bh = blockIdx.y;
    const int q0 = qb * 64;
    const float scale = 0.08838834764831845f;

    const float* Qg = g_Qt + (size_t)bh * HDIM * SEQ;
    const float* Kg = g_Kt + (size_t)bh * HDIM * SEQ;
    const float* Vg = g_V  + (size_t)bh * SEQ * HDIM;

#pragma unroll
    for (int it = 0; it < 8; it++) {
        int idx = t + it * 256;
        int d = idx >> 4, s4 = (idx & 15) * 4;
        float4 v = *(const float4*)&Qg[(size_t)d * SEQ + q0 + s4];
        v.x *= scale; v.y *= scale; v.z *= scale; v.w *= scale;
        *(float4*)&Qs[d * 64 + s4] = v;
    }

    float m_r[4], l_r[4], O[4][8];
#pragma unroll
    for (int i = 0; i < 4; i++) {
        m_r[i] = -1e30f; l_r[i] = 0.f;
#pragma unroll
        for (int j = 0; j < 8; j++) O[i][j] = 0.f;
    }

    for (int kb = 0; kb <= qb; kb++) {
        const int k0 = kb * 64;
        __syncthreads();
#pragma unroll
        for (int it = 0; it < 8; it++) {
            int idx = t + it * 256;
            int d = idx >> 4, c4 = (idx & 15) * 4;
            *(float4*)&KV[d * 64 + c4] =
                *(const float4*)&Kg[(size_t)d * SEQ + k0 + c4];
        }
        __syncthreads();

        float S[4][4];
#pragma unroll
        for (int i = 0; i < 4; i++)
#pragma unroll
            for (int j = 0; j < 4; j++) S[i][j] = 0.f;

        for (int d = 0; d < 128; d++) {
            float a[4], b[4];
            *(float4*)a = *(const float4*)&Qs[d * 64 + 4 * ty];
            *(float4*)b = *(const float4*)&KV[d * 64 + 4 * tx];
#pragma unroll
            for (int i = 0; i < 4; i++)
#pragma unroll
                for (int j = 0; j < 4; j++)
                    S[i][j] += a[i] * b[j];
        }

        if (kb == qb) {
#pragma unroll
            for (int i = 0; i < 4; i++)
#pragma unroll
                for (int j = 0; j < 4; j++)
                    if (4 * tx + j > 4 * ty + i) S[i][j] = -1e30f;
        }

#pragma unroll
        for (int i = 0; i < 4; i++) {
            float rmax = fmaxf(fmaxf(S[i][0], S[i][1]), fmaxf(S[i][2], S[i][3]));
#pragma unroll
            for (int off = 1; off < 16; off <<= 1)
                rmax = fmaxf(rmax, __shfl_xor_sync(0xffffffffu, rmax, off));
            float mnew = fmaxf(m_r[i], rmax);
            float corr = __expf(m_r[i] - mnew);
            float p[4], rsum = 0.f;
#pragma unroll
            for (int j = 0; j < 4; j++) {
                p[j] = __expf(S[i][j] - mnew);
                rsum += p[j];
            }
#pragma unroll
            for (int off = 1; off < 16; off <<= 1)
                rsum += __shfl_xor_sync(0xffffffffu, rsum, off);
            l_r[i] = l_r[i] * corr + rsum;
            m_r[i] = mnew;
#pragma unroll
            for (int j = 0; j < 8; j++) O[i][j] *= corr;
#pragma unroll
            for (int j = 0; j < 4; j++)
                Ps[(4 * tx + j) * 65 + 4 * ty + i] = p[j];
        }

        __syncthreads();
#pragma unroll
        for (int it = 0; it < 8; it++) {
            int idx = t + it * 256;
            int k = idx >> 5, d4 = (idx & 31) * 4;
            *(float4*)&KV[k * 132 + d4] =
                *(const float4*)&Vg[(size_t)(k0 + k) * HDIM + d4];
        }
        __syncthreads();

        for (int k = 0; k < 64; k++) {
            float p0 = Ps[k * 65 + 4 * ty + 0];
            float p1 = Ps[k * 65 + 4 * ty + 1];
            float p2 = Ps[k * 65 + 4 * ty + 2];
            float p3 = Ps[k * 65 + 4 * ty + 3];
            float v[8];
            *(float4*)&v[0] = *(const float4*)&KV[k * 132 + 8 * tx];
            *(float4*)&v[4] = *(const float4*)&KV[k * 132 + 8 * tx + 4];
#pragma unroll
            for (int j = 0; j < 8; j++) {
                O[0][j] += p0 * v[j];
                O[1][j] += p1 * v[j];
                O[2][j] += p2 * v[j];
                O[3][j] += p3 * v[j];
            }
        }
    }

    const int b = bh >> 4, h = bh & 15;
#pragma unroll
    for (int i = 0; i < 4; i++) {
        float inv = 1.f / l_r[i];
        int row = q0 + 4 * ty + i;
        float* dst = &g_attn[(size_t)((b * SEQ + row) * NHEAD + h) * HDIM + 8 * tx];
        float4 o0, o1;
        o0.x = O[i][0] * inv; o0.y = O[i][1] * inv;
        o0.z = O[i][2] * inv; o0.w = O[i][3] * inv;
        o1.x = O[i][4] * inv; o1.y = O[i][5] * inv;
        o1.z = O[i][6] * inv; o1.w = O[i][7] * inv;
        *(float4*)dst       = o0;
        *(float4*)(dst + 4) = o1;
    }
}

// ---------------------------------------------------------------------------
extern "C" void kernel_launch(void* const* d_in, const int* in_sizes, int n_in,
                              void* d_out, int out_size)
{
    const float* x  = (const float*)d_in[0];
    const float* Wq = (const float*)d_in[1];
    const float* bq = (const float*)d_in[2];
    const float* Wk = (const float*)d_in[3];
    const float* bk = (const float*)d_in[4];
    const float* Wv = (const float*)d_in[5];
    const float* bv = (const float*)d_in[6];
    const float* Wo = (const float*)d_in[7];
    const float* bo = (const float*)d_in[8];
    float* out = (float*)d_out;

    float *qt, *kt, *vv, *attn;
    cudaGetSymbolAddress((void**)&qt,   g_Qt);
    cudaGetSymbolAddress((void**)&kt,   g_Kt);
    cudaGetSymbolAddress((void**)&vv,   g_V);
    cudaGetSymbolAddress((void**)&attn, g_attn);

    const size_t gemm_smem = BUF_FLOATS * 2 * sizeof(float); // 64 KB
    cudaFuncSetAttribute(gemm_tf32_kernel,
                         cudaFuncAttributeMaxDynamicSharedMemorySize, (int)gemm_smem);
    const size_t attn_smem = SMEM_FLOATS * sizeof(float);    // 83,200 B
    cudaFuncSetAttribute(attn_kernel,
                         cudaFuncAttributeMaxDynamicSharedMemorySize, (int)attn_smem);

    dim3 gemm_grid(HID / 128, MROWS / 128); // (16, 32)
    gemm_tf32_kernel<<<gemm_grid, 256, gemm_smem>>>(x, Wq, bq, qt, 1);
    gemm_tf32_kernel<<<gemm_grid, 256, gemm_smem>>>(x, Wk, bk, kt, 1);
    gemm_tf32_kernel<<<gemm_grid, 256, gemm_smem>>>(x, Wv, bv, vv, 2);
    attn_kernel<<<dim3(SEQ / 64, BH), 256, attn_smem>>>();
    gemm_tf32_kernel<<<gemm_grid, 256, gemm_smem>>>(attn, Wo, bo, out, 0);
}

// round 3
// speedup vs baseline: 3.7049x; 1.6204x over previous
#include <cuda_runtime.h>
#include <cstdint>

#define HID   2048
#define MROWS 4096   // B*S
#define NHEAD 16
#define HDIM  128
#define SEQ   2048
#define BH    32     // B*NHEAD

// Scratch (no allocations allowed)
__device__ float g_Q [BH * SEQ * HDIM];       // [bh][s][d]
__device__ float g_K [BH * SEQ * HDIM];       // [bh][s][d]
__device__ float g_Vt[BH * HDIM * SEQ];       // [bh][d][s]
__device__ float g_attn[(size_t)MROWS * HID]; // [B*S][nh*hd]

// ---------------------------------------------------------------------------
// common helpers
// ---------------------------------------------------------------------------
__device__ __forceinline__ void cp_async16(void* smem_dst, const void* gmem_src) {
    uint32_t s = (uint32_t)__cvta_generic_to_shared(smem_dst);
    asm volatile("cp.async.cg.shared.global [%0], [%1], 16;\n" :: "r"(s), "l"(gmem_src));
}
__device__ __forceinline__ uint32_t f2tf32(float f) {
    uint32_t u;
    asm("cvt.rna.tf32.f32 %0, %1;" : "=r"(u) : "f"(f));
    return u;
}
__device__ __forceinline__ void mma_tf32(float* d, const uint32_t* a, const uint32_t* b) {
    asm volatile(
        "mma.sync.aligned.m16n8k8.row.col.f32.tf32.tf32.f32 "
        "{%0,%1,%2,%3}, {%4,%5,%6,%7}, {%8,%9}, {%0,%1,%2,%3};"
        : "+f"(d[0]), "+f"(d[1]), "+f"(d[2]), "+f"(d[3])
        : "r"(a[0]), "r"(a[1]), "r"(a[2]), "r"(a[3]), "r"(b[0]), "r"(b[1]));
}
// swizzle a chunk index within its 8-chunk (128B) group by row low bits
__device__ __forceinline__ int swz(int row, int ck) {
    return (ck & ~7) | ((ck ^ row) & 7);
}

// ---------------------------------------------------------------------------
// tf32 tensor-core GEMM (unchanged math): C[m,n] = sum_k A[m,k]*W[n,k] + b[n]
// modes: 0 row-major; 1 -> [bh][d][s]; 2 -> [bh][s][d]
// ---------------------------------------------------------------------------
#define BK 32
#define NKT (HID / BK)   // 64
#define BUF_FLOATS 8192

__global__ __launch_bounds__(256, 2)
void gemm_tf32_kernel(const float* __restrict__ A,
                      const float* __restrict__ W,
                      const float* __restrict__ bias,
                      float* __restrict__ out,
                      int mode)
{
    extern __shared__ float sm[];
    const int t    = threadIdx.x;
    const int lane = t & 31;
    const int wid  = t >> 5;
    const int wm   = wid & 3;
    const int wn   = wid >> 2;
    const int m0   = blockIdx.y * 128;
    const int n0   = blockIdx.x * 128;
    const int r = lane >> 2;
    const int c = lane & 3;

    float acc[2][8][4];
#pragma unroll
    for (int i = 0; i < 2; i++)
#pragma unroll
        for (int j = 0; j < 8; j++)
#pragma unroll
            for (int e = 0; e < 4; e++) acc[i][j][e] = 0.f;

    auto issue_tile = [&](int kt, int buf) {
        float* As = sm + buf * BUF_FLOATS;
        float* Ws = As + 4096;
        const int k0 = kt * BK;
#pragma unroll
        for (int i = 0; i < 4; i++) {
            int id  = t + i * 256;
            int row = id >> 3;
            int ck  = id & 7;
            int swk = (ck ^ (row & 7)) << 2;
            cp_async16(As + row * 32 + swk,
                       A + (size_t)(m0 + row) * HID + k0 + ck * 4);
            cp_async16(Ws + row * 32 + swk,
                       W + (size_t)(n0 + row) * HID + k0 + ck * 4);
        }
        asm volatile("cp.async.commit_group;\n");
    };

    issue_tile(0, 0);

    for (int kt = 0; kt < NKT; kt++) {
        if (kt + 1 < NKT) {
            issue_tile(kt + 1, (kt + 1) & 1);
            asm volatile("cp.async.wait_group 1;\n");
        } else {
            asm volatile("cp.async.wait_group 0;\n");
        }
        __syncthreads();

        const float* As = sm + (kt & 1) * BUF_FLOATS;
        const float* Ws = As + 4096;

#pragma unroll
        for (int ks = 0; ks < 4; ks++) {
            uint32_t af[2][4];
#pragma unroll
            for (int i = 0; i < 2; i++) {
                int mrow = wm * 32 + i * 16 + r;
                int ch0 = ((2 * ks) ^ r) << 2;
                int ch1 = ((2 * ks + 1) ^ r) << 2;
                af[i][0] = f2tf32(As[mrow * 32 + ch0 + c]);
                af[i][1] = f2tf32(As[(mrow + 8) * 32 + ch0 + c]);
                af[i][2] = f2tf32(As[mrow * 32 + ch1 + c]);
                af[i][3] = f2tf32(As[(mrow + 8) * 32 + ch1 + c]);
            }
            uint32_t bf[8][2];
#pragma unroll
            for (int j = 0; j < 8; j++) {
                int nrow = wn * 64 + j * 8 + r;
                int ch0 = ((2 * ks) ^ r) << 2;
                int ch1 = ((2 * ks + 1) ^ r) << 2;
                bf[j][0] = f2tf32(Ws[nrow * 32 + ch0 + c]);
                bf[j][1] = f2tf32(Ws[nrow * 32 + ch1 + c]);
            }
#pragma unroll
            for (int i = 0; i < 2; i++)
#pragma unroll
                for (int j = 0; j < 8; j++)
                    mma_tf32(acc[i][j], af[i], bf[j]);
        }
        __syncthreads();
    }

#pragma unroll
    for (int i = 0; i < 2; i++) {
        int r0 = m0 + wm * 32 + i * 16 + r;
        int r1 = r0 + 8;
#pragma unroll
        for (int j = 0; j < 8; j++) {
            int nb = n0 + wn * 64 + j * 8 + 2 * c;
            float b0 = bias[nb], b1 = bias[nb + 1];
            float d00 = acc[i][j][0] + b0, d01 = acc[i][j][1] + b1;
            float d10 = acc[i][j][2] + b0, d11 = acc[i][j][3] + b1;
            if (mode == 0) {
                *(float2*)&out[(size_t)r0 * HID + nb] = make_float2(d00, d01);
                *(float2*)&out[(size_t)r1 * HID + nb] = make_float2(d10, d11);
            } else if (mode == 1) {
                int h = nb >> 7, d = nb & 127;
                int b_0 = r0 >> 11, s_0 = r0 & 2047;
                int b_1 = r1 >> 11, s_1 = r1 & 2047;
                size_t base0 = (size_t)((b_0 * NHEAD + h) * HDIM + d) * SEQ;
                size_t base1 = (size_t)((b_1 * NHEAD + h) * HDIM + d) * SEQ;
                out[base0 + s_0]       = d00;
                out[base0 + SEQ + s_0] = d01;
                out[base1 + s_1]       = d10;
                out[base1 + SEQ + s_1] = d11;
            } else {
                int h = nb >> 7, d = nb & 127;
                int b_0 = r0 >> 11, s_0 = r0 & 2047;
                int b_1 = r1 >> 11, s_1 = r1 & 2047;
                *(float2*)&out[(size_t)((b_0 * NHEAD + h) * SEQ + s_0) * HDIM + d] =
                    make_float2(d00, d01);
                *(float2*)&out[(size_t)((b_1 * NHEAD + h) * SEQ + s_1) * HDIM + d] =
                    make_float2(d10, d11);
            }
        }
    }
}

// ---------------------------------------------------------------------------
// Tensor-core flash attention (causal, tf32 warp MMA).
// CTA: 128 q-rows of one (b,h), 8 warps x 16 rows. K/V tiles of 64 keys,
// cp.async double-buffered. P round-trips via per-warp smem.
// smem (floats): Qs 16384 | Ks 2x8192 | Vs 2x8192 | Ps 8192  = 224KB
// ---------------------------------------------------------------------------
#define QS_OFF 0
#define KS_OFF 16384
#define VS_OFF 32768
#define PS_OFF 49152
#define ATTN_SMEM_FLOATS 57344

__global__ __launch_bounds__(256, 1)
void attn_tc_kernel()
{
    extern __shared__ float sm[];
    float* Qs = sm + QS_OFF;
    float* Ps = sm + PS_OFF;

    const int t    = threadIdx.x;
    const int lane = t & 31;
    const int w    = t >> 5;       // 0..7
    const int r    = lane >> 2;    // 0..7
    const int c    = lane & 3;     // 0..3
    const int qbI  = 15 - blockIdx.x;  // heavy blocks first
    const int bh   = blockIdx.y;
    const int q0   = qbI * 128;
    const int nkb  = 2 * qbI + 2;
    const float scale = 0.08838834764831845f; // 1/sqrt(128)

    const float* Qg = g_Q  + (size_t)bh * SEQ * HDIM;
    const float* Kg = g_K  + (size_t)bh * SEQ * HDIM;
    const float* Vg = g_Vt + (size_t)bh * HDIM * SEQ;

    auto issueKV = [&](int kb, int buf) {
        float* Ksb = sm + KS_OFF + buf * 8192;
        float* Vsb = sm + VS_OFF + buf * 8192;
        const int k0 = kb * 64;
#pragma unroll
        for (int i = 0; i < 8; i++) {         // K: 64 rows x 32 chunks
            int id = t + i * 256;
            int row = id >> 5, ck = id & 31;
            cp_async16(Ksb + row * 128 + swz(row & 7, ck) * 4,
                       Kg + (size_t)(k0 + row) * HDIM + ck * 4);
        }
#pragma unroll
        for (int i = 0; i < 8; i++) {         // V: 128 d-rows x 16 chunks
            int id = t + i * 256;
            int row = id >> 4, ck = id & 15;
            cp_async16(Vsb + row * 64 + swz(row & 7, ck) * 4,
                       Vg + (size_t)row * SEQ + k0 + ck * 4);
        }
        asm volatile("cp.async.commit_group;\n");
    };

    // Prologue: Q (one-time) + KV(0) in group 0
#pragma unroll
    for (int i = 0; i < 16; i++) {            // Q: 128 rows x 32 chunks
        int id = t + i * 256;
        int row = id >> 5, ck = id & 31;
        cp_async16(Qs + row * 128 + swz(row & 7, ck) * 4,
                   Qg + (size_t)(q0 + row) * HDIM + ck * 4);
    }
    issueKV(0, 0);

    float m_s[2], l_s[2], O[16][4];
#pragma unroll
    for (int e = 0; e < 2; e++) { m_s[e] = -1e30f; l_s[e] = 0.f; }
#pragma unroll
    for (int j = 0; j < 16; j++)
#pragma unroll
        for (int e = 0; e < 4; e++) O[j][e] = 0.f;

    const int qrow = w * 16 + r;

    for (int kb = 0; kb < nkb; kb++) {
        const int buf = kb & 1;
        const int k0  = kb * 64;
        if (kb + 1 < nkb) {
            issueKV(kb + 1, (kb + 1) & 1);
            asm volatile("cp.async.wait_group 1;\n");
        } else {
            asm volatile("cp.async.wait_group 0;\n");
        }
        __syncthreads();

        const float* Ksb = sm + KS_OFF + buf * 8192;
        const float* Vsb = sm + VS_OFF + buf * 8192;

        // ---- S = Q K^T ----
        float sacc[8][4];
#pragma unroll
        for (int j = 0; j < 8; j++)
#pragma unroll
            for (int e = 0; e < 4; e++) sacc[j][e] = 0.f;

#pragma unroll
        for (int ks = 0; ks < 16; ks++) {
            const int ch0 = swz(r, 2 * ks) * 4;
            const int ch1 = swz(r, 2 * ks + 1) * 4;
            uint32_t a[4];
            a[0] = f2tf32(Qs[qrow * 128 + ch0 + c]);
            a[1] = f2tf32(Qs[(qrow + 8) * 128 + ch0 + c]);
            a[2] = f2tf32(Qs[qrow * 128 + ch1 + c]);
            a[3] = f2tf32(Qs[(qrow + 8) * 128 + ch1 + c]);
#pragma unroll
            for (int j = 0; j < 8; j++) {
                const int krow = j * 8 + r;
                uint32_t b[2];
                b[0] = f2tf32(Ksb[krow * 128 + ch0 + c]);
                b[1] = f2tf32(Ksb[krow * 128 + ch1 + c]);
                mma_tf32(sacc[j], a, b);
            }
        }

        // ---- scale + causal mask ----
        const bool need_mask = (k0 + 63 > q0);
#pragma unroll
        for (int j = 0; j < 8; j++)
#pragma unroll
            for (int e = 0; e < 4; e++) {
                float v = sacc[j][e] * scale;
                if (need_mask) {
                    int col = k0 + j * 8 + 2 * c + (e & 1);
                    int row = q0 + qrow + ((e & 2) ? 8 : 0);
                    if (col > row) v = -1e30f;
                }
                sacc[j][e] = v;
            }

        // ---- online softmax (rows r and r+8) ----
#pragma unroll
        for (int half = 0; half < 2; half++) {
            const int e0 = half * 2;
            float rmax = -1e30f;
#pragma unroll
            for (int j = 0; j < 8; j++)
                rmax = fmaxf(rmax, fmaxf(sacc[j][e0], sacc[j][e0 + 1]));
            rmax = fmaxf(rmax, __shfl_xor_sync(0xffffffffu, rmax, 1));
            rmax = fmaxf(rmax, __shfl_xor_sync(0xffffffffu, rmax, 2));
            float mnew = fmaxf(m_s[half], rmax);
            float corr = __expf(m_s[half] - mnew);
            float rsum = 0.f;
#pragma unroll
            for (int j = 0; j < 8; j++) {
                float p0 = __expf(sacc[j][e0] - mnew);
                float p1 = __expf(sacc[j][e0 + 1] - mnew);
                sacc[j][e0] = p0; sacc[j][e0 + 1] = p1;
                rsum += p0 + p1;
            }
            rsum += __shfl_xor_sync(0xffffffffu, rsum, 1);
            rsum += __shfl_xor_sync(0xffffffffu, rsum, 2);
            l_s[half] = l_s[half] * corr + rsum;
            m_s[half] = mnew;
#pragma unroll
            for (int j = 0; j < 16; j++) {
                O[j][e0]     *= corr;
                O[j][e0 + 1] *= corr;
            }
        }

        // ---- P -> smem (per-warp region) ----
#pragma unroll
        for (int j = 0; j < 8; j++) {
            int ck = 2 * j + (c >> 1);
            int off = swz(r, ck) * 4 + (c & 1) * 2;
            *(float2*)&Ps[qrow * 64 + off]       = make_float2(sacc[j][0], sacc[j][1]);
            *(float2*)&Ps[(qrow + 8) * 64 + off] = make_float2(sacc[j][2], sacc[j][3]);
        }
        __syncwarp();

        // ---- O += P V ----
#pragma unroll
        for (int ks = 0; ks < 8; ks++) {
            const int ch0 = swz(r, 2 * ks) * 4;
            const int ch1 = swz(r, 2 * ks + 1) * 4;
            uint32_t a[4];
            a[0] = f2tf32(Ps[qrow * 64 + ch0 + c]);
            a[1] = f2tf32(Ps[(qrow + 8) * 64 + ch0 + c]);
            a[2] = f2tf32(Ps[qrow * 64 + ch1 + c]);
            a[3] = f2tf32(Ps[(qrow + 8) * 64 + ch1 + c]);
#pragma unroll
            for (int j = 0; j < 16; j++) {
                const int vrow = j * 8 + r;
                uint32_t b[2];
                b[0] = f2tf32(Vsb[vrow * 64 + ch0 + c]);
                b[1] = f2tf32(Vsb[vrow * 64 + ch1 + c]);
                mma_tf32(O[j], a, b);
            }
        }
        __syncthreads();
    }

    // ---- epilogue: O/l -> g_attn[m][h*128+d] ----
    const int b = bh >> 4, h = bh & 15;
    const float inv0 = 1.f / l_s[0];
    const float inv1 = 1.f / l_s[1];
    const int row0 = q0 + qrow, row1 = row0 + 8;
#pragma unroll
    for (int j = 0; j < 16; j++) {
        int n = h * HDIM + j * 8 + 2 * c;
        *(float2*)&g_attn[(size_t)(b * SEQ + row0) * HID + n] =
            make_float2(O[j][0] * inv0, O[j][1] * inv0);
        *(float2*)&g_attn[(size_t)(b * SEQ + row1) * HID + n] =
            make_float2(O[j][2] * inv1, O[j][3] * inv1);
    }
}

// ---------------------------------------------------------------------------
extern "C" void kernel_launch(void* const* d_in, const int* in_sizes, int n_in,
                              void* d_out, int out_size)
{
    const float* x  = (const float*)d_in[0];
    const float* Wq = (const float*)d_in[1];
    const float* bq = (const float*)d_in[2];
    const float* Wk = (const float*)d_in[3];
    const float* bk = (const float*)d_in[4];
    const float* Wv = (const float*)d_in[5];
    const float* bv = (const float*)d_in[6];
    const float* Wo = (const float*)d_in[7];
    const float* bo = (const float*)d_in[8];
    float* out = (float*)d_out;

    float *q, *k, *vt, *attn;
    cudaGetSymbolAddress((void**)&q,    g_Q);
    cudaGetSymbolAddress((void**)&k,    g_K);
    cudaGetSymbolAddress((void**)&vt,   g_Vt);
    cudaGetSymbolAddress((void**)&attn, g_attn);

    const size_t gemm_smem = BUF_FLOATS * 2 * sizeof(float);        // 64 KB
    cudaFuncSetAttribute(gemm_tf32_kernel,
                         cudaFuncAttributeMaxDynamicSharedMemorySize, (int)gemm_smem);
    const size_t attn_smem = ATTN_SMEM_FLOATS * sizeof(float);      // 224 KB
    cudaFuncSetAttribute(attn_tc_kernel,
                         cudaFuncAttributeMaxDynamicSharedMemorySize, (int)attn_smem);

    dim3 gemm_grid(HID / 128, MROWS / 128); // (16, 32)
    gemm_tf32_kernel<<<gemm_grid, 256, gemm_smem>>>(x, Wq, bq, q, 2);
    gemm_tf32_kernel<<<gemm_grid, 256, gemm_smem>>>(x, Wk, bk, k, 2);
    gemm_tf32_kernel<<<gemm_grid, 256, gemm_smem>>>(x, Wv, bv, vt, 1);
    attn_tc_kernel<<<dim3(SEQ / 128, BH), 256, attn_smem>>>();
    gemm_tf32_kernel<<<gemm_grid, 256, gemm_smem>>>(attn, Wo, bo, out, 0);
}

// round 4
// speedup vs baseline: 4.5106x; 1.2175x over previous
#include <cuda_runtime.h>
#include <cstdint>

#define HID   2048
#define MROWS 4096   // B*S
#define NHEAD 16
#define HDIM  128
#define SEQ   2048
#define BH    32     // B*NHEAD

// Scratch (no allocations allowed)
__device__ float g_Q [BH * SEQ * HDIM];       // [bh][s][d]   (tf32-rounded)
__device__ float g_K [BH * SEQ * HDIM];       // [bh][s][d]   (tf32-rounded)
__device__ float g_Vt[BH * HDIM * SEQ];       // [bh][d][s]   (tf32-rounded)
__device__ float g_attn[(size_t)MROWS * HID]; // [B*S][nh*hd] (tf32-rounded)
__device__ float g_xr[(size_t)MROWS * HID];   // rounded x
__device__ float g_Wr[4ull * HID * HID];      // rounded Wq,Wk,Wv,Wo

// ---------------------------------------------------------------------------
// helpers
// ---------------------------------------------------------------------------
__device__ __forceinline__ void cp_async16(void* smem_dst, const void* gmem_src) {
    uint32_t s = (uint32_t)__cvta_generic_to_shared(smem_dst);
    asm volatile("cp.async.cg.shared.global [%0], [%1], 16;\n" :: "r"(s), "l"(gmem_src));
}
__device__ __forceinline__ float rnd_tf32(float f) {
    uint32_t u;
    asm("cvt.rna.tf32.f32 %0, %1;" : "=r"(u) : "f"(f));
    return __uint_as_float(u);
}
__device__ __forceinline__ void mma_tf32(float* d, const uint32_t* a, const uint32_t* b) {
    asm volatile(
        "mma.sync.aligned.m16n8k8.row.col.f32.tf32.tf32.f32 "
        "{%0,%1,%2,%3}, {%4,%5,%6,%7}, {%8,%9}, {%0,%1,%2,%3};"
        : "+f"(d[0]), "+f"(d[1]), "+f"(d[2]), "+f"(d[3])
        : "r"(a[0]), "r"(a[1]), "r"(a[2]), "r"(a[3]), "r"(b[0]), "r"(b[1]));
}
__device__ __forceinline__ int swz(int row, int ck) {
    return (ck & ~7) | ((ck ^ row) & 7);
}

// ---------------------------------------------------------------------------
// elementwise tf32 pre-round (float4 grid-stride)
// ---------------------------------------------------------------------------
__global__ __launch_bounds__(256)
void round_tf32_kernel(const float* __restrict__ in, float* __restrict__ out, int n4)
{
    int i = blockIdx.x * blockDim.x + threadIdx.x;
    if (i < n4) {
        float4 v = ((const float4*)in)[i];
        v.x = rnd_tf32(v.x); v.y = rnd_tf32(v.y);
        v.z = rnd_tf32(v.z); v.w = rnd_tf32(v.w);
        ((float4*)out)[i] = v;
    }
}

// ---------------------------------------------------------------------------
// tf32 GEMM, raw-bit operands (inputs pre-rounded).
// C[m,n] = sum_k A[m,k]*W[n,k] + bias[n]
// modes: 0 row-major (fp32); 1 -> [bh][d][s] rounded; 2 -> [bh][s][d] rounded
// ---------------------------------------------------------------------------
#define BK 32
#define NKT (HID / BK)   // 64
#define BUF_FLOATS 8192

__global__ __launch_bounds__(256, 2)
void gemm_tf32_kernel(const float* __restrict__ A,
                      const float* __restrict__ W,
                      const float* __restrict__ bias,
                      float* __restrict__ out,
                      int mode)
{
    extern __shared__ float sm[];
    const int t    = threadIdx.x;
    const int lane = t & 31;
    const int wid  = t >> 5;
    const int wm   = wid & 3;
    const int wn   = wid >> 2;
    const int m0   = blockIdx.y * 128;
    const int n0   = blockIdx.x * 128;
    const int r = lane >> 2;
    const int c = lane & 3;

    float acc[2][8][4];
#pragma unroll
    for (int i = 0; i < 2; i++)
#pragma unroll
        for (int j = 0; j < 8; j++)
#pragma unroll
            for (int e = 0; e < 4; e++) acc[i][j][e] = 0.f;

    auto issue_tile = [&](int kt, int buf) {
        float* As = sm + buf * BUF_FLOATS;
        float* Ws = As + 4096;
        const int k0 = kt * BK;
#pragma unroll
        for (int i = 0; i < 4; i++) {
            int id  = t + i * 256;
            int row = id >> 3;
            int ck  = id & 7;
            int swk = (ck ^ (row & 7)) << 2;
            cp_async16(As + row * 32 + swk,
                       A + (size_t)(m0 + row) * HID + k0 + ck * 4);
            cp_async16(Ws + row * 32 + swk,
                       W + (size_t)(n0 + row) * HID + k0 + ck * 4);
        }
        asm volatile("cp.async.commit_group;\n");
    };

    issue_tile(0, 0);

    for (int kt = 0; kt < NKT; kt++) {
        if (kt + 1 < NKT) {
            issue_tile(kt + 1, (kt + 1) & 1);
            asm volatile("cp.async.wait_group 1;\n");
        } else {
            asm volatile("cp.async.wait_group 0;\n");
        }
        __syncthreads();

        const uint32_t* As = (const uint32_t*)(sm + (kt & 1) * BUF_FLOATS);
        const uint32_t* Ws = As + 4096;

#pragma unroll
        for (int ks = 0; ks < 4; ks++) {
            const int ch0 = ((2 * ks) ^ r) << 2;
            const int ch1 = ((2 * ks + 1) ^ r) << 2;
            uint32_t af[2][4];
#pragma unroll
            for (int i = 0; i < 2; i++) {
                int mrow = wm * 32 + i * 16 + r;
                af[i][0] = As[mrow * 32 + ch0 + c];
                af[i][1] = As[(mrow + 8) * 32 + ch0 + c];
                af[i][2] = As[mrow * 32 + ch1 + c];
                af[i][3] = As[(mrow + 8) * 32 + ch1 + c];
            }
            uint32_t bf[8][2];
#pragma unroll
            for (int j = 0; j < 8; j++) {
                int nrow = wn * 64 + j * 8 + r;
                bf[j][0] = Ws[nrow * 32 + ch0 + c];
                bf[j][1] = Ws[nrow * 32 + ch1 + c];
            }
#pragma unroll
            for (int i = 0; i < 2; i++)
#pragma unroll
                for (int j = 0; j < 8; j++)
                    mma_tf32(acc[i][j], af[i], bf[j]);
        }
        __syncthreads();
    }

#pragma unroll
    for (int i = 0; i < 2; i++) {
        int r0 = m0 + wm * 32 + i * 16 + r;
        int r1 = r0 + 8;
#pragma unroll
        for (int j = 0; j < 8; j++) {
            int nb = n0 + wn * 64 + j * 8 + 2 * c;
            float b0 = bias[nb], b1 = bias[nb + 1];
            float d00 = acc[i][j][0] + b0, d01 = acc[i][j][1] + b1;
            float d10 = acc[i][j][2] + b0, d11 = acc[i][j][3] + b1;
            if (mode == 0) {
                *(float2*)&out[(size_t)r0 * HID + nb] = make_float2(d00, d01);
                *(float2*)&out[(size_t)r1 * HID + nb] = make_float2(d10, d11);
            } else if (mode == 1) {
                d00 = rnd_tf32(d00); d01 = rnd_tf32(d01);
                d10 = rnd_tf32(d10); d11 = rnd_tf32(d11);
                int h = nb >> 7, d = nb & 127;
                int b_0 = r0 >> 11, s_0 = r0 & 2047;
                int b_1 = r1 >> 11, s_1 = r1 & 2047;
                size_t base0 = (size_t)((b_0 * NHEAD + h) * HDIM + d) * SEQ;
                size_t base1 = (size_t)((b_1 * NHEAD + h) * HDIM + d) * SEQ;
                out[base0 + s_0]       = d00;
                out[base0 + SEQ + s_0] = d01;
                out[base1 + s_1]       = d10;
                out[base1 + SEQ + s_1] = d11;
            } else {
                d00 = rnd_tf32(d00); d01 = rnd_tf32(d01);
                d10 = rnd_tf32(d10); d11 = rnd_tf32(d11);
                int h = nb >> 7, d = nb & 127;
                int b_0 = r0 >> 11, s_0 = r0 & 2047;
                int b_1 = r1 >> 11, s_1 = r1 & 2047;
                *(float2*)&out[(size_t)((b_0 * NHEAD + h) * SEQ + s_0) * HDIM + d] =
                    make_float2(d00, d01);
                *(float2*)&out[(size_t)((b_1 * NHEAD + h) * SEQ + s_1) * HDIM + d] =
                    make_float2(d10, d11);
            }
        }
    }
}

// ---------------------------------------------------------------------------
// Tensor-core flash attention (causal, tf32). Raw-bit operands everywhere;
// P rounded once when spilled to smem.
// smem (floats): Qs 16384 | Ks 2x8192 | Vs 2x8192 | Ps 8192 = 224KB
// ---------------------------------------------------------------------------
#define QS_OFF 0
#define KS_OFF 16384
#define VS_OFF 32768
#define PS_OFF 49152
#define ATTN_SMEM_FLOATS 57344

__global__ __launch_bounds__(256, 1)
void attn_tc_kernel()
{
    extern __shared__ float sm[];
    const uint32_t* Qs = (const uint32_t*)(sm + QS_OFF);
    float* Ps = sm + PS_OFF;

    const int t    = threadIdx.x;
    const int lane = t & 31;
    const int w    = t >> 5;
    const int r    = lane >> 2;
    const int c    = lane & 3;
    const int qbI  = 15 - blockIdx.x;
    const int bh   = blockIdx.y;
    const int q0   = qbI * 128;
    const int nkb  = 2 * qbI + 2;
    const float scale = 0.08838834764831845f; // 1/sqrt(128)

    const float* Qg = g_Q  + (size_t)bh * SEQ * HDIM;
    const float* Kg = g_K  + (size_t)bh * SEQ * HDIM;
    const float* Vg = g_Vt + (size_t)bh * HDIM * SEQ;

    auto issueKV = [&](int kb, int buf) {
        float* Ksb = sm + KS_OFF + buf * 8192;
        float* Vsb = sm + VS_OFF + buf * 8192;
        const int k0 = kb * 64;
#pragma unroll
        for (int i = 0; i < 8; i++) {
            int id = t + i * 256;
            int row = id >> 5, ck = id & 31;
            cp_async16(Ksb + row * 128 + swz(row & 7, ck) * 4,
                       Kg + (size_t)(k0 + row) * HDIM + ck * 4);
        }
#pragma unroll
        for (int i = 0; i < 8; i++) {
            int id = t + i * 256;
            int row = id >> 4, ck = id & 15;
            cp_async16(Vsb + row * 64 + swz(row & 7, ck) * 4,
                       Vg + (size_t)row * SEQ + k0 + ck * 4);
        }
        asm volatile("cp.async.commit_group;\n");
    };

#pragma unroll
    for (int i = 0; i < 16; i++) {
        int id = t + i * 256;
        int row = id >> 5, ck = id & 31;
        cp_async16((float*)Qs + row * 128 + swz(row & 7, ck) * 4,
                   Qg + (size_t)(q0 + row) * HDIM + ck * 4);
    }
    issueKV(0, 0);

    float m_s[2], l_s[2], O[16][4];
#pragma unroll
    for (int e = 0; e < 2; e++) { m_s[e] = -1e30f; l_s[e] = 0.f; }
#pragma unroll
    for (int j = 0; j < 16; j++)
#pragma unroll
        for (int e = 0; e < 4; e++) O[j][e] = 0.f;

    const int qrow = w * 16 + r;

    for (int kb = 0; kb < nkb; kb++) {
        const int buf = kb & 1;
        const int k0  = kb * 64;
        if (kb + 1 < nkb) {
            issueKV(kb + 1, (kb + 1) & 1);
            asm volatile("cp.async.wait_group 1;\n");
        } else {
            asm volatile("cp.async.wait_group 0;\n");
        }
        __syncthreads();

        const uint32_t* Ksb = (const uint32_t*)(sm + KS_OFF + buf * 8192);
        const uint32_t* Vsb = (const uint32_t*)(sm + VS_OFF + buf * 8192);

        // ---- S = Q K^T ----
        float sacc[8][4];
#pragma unroll
        for (int j = 0; j < 8; j++)
#pragma unroll
            for (int e = 0; e < 4; e++) sacc[j][e] = 0.f;

#pragma unroll
        for (int ks = 0; ks < 16; ks++) {
            const int ch0 = swz(r, 2 * ks) * 4;
            const int ch1 = swz(r, 2 * ks + 1) * 4;
            uint32_t a[4];
            a[0] = Qs[qrow * 128 + ch0 + c];
            a[1] = Qs[(qrow + 8) * 128 + ch0 + c];
            a[2] = Qs[qrow * 128 + ch1 + c];
            a[3] = Qs[(qrow + 8) * 128 + ch1 + c];
#pragma unroll
            for (int j = 0; j < 8; j++) {
                const int krow = j * 8 + r;
                uint32_t b[2];
                b[0] = Ksb[krow * 128 + ch0 + c];
                b[1] = Ksb[krow * 128 + ch1 + c];
                mma_tf32(sacc[j], a, b);
            }
        }

        // ---- scale + causal mask ----
        const bool need_mask = (k0 + 63 > q0);
#pragma unroll
        for (int j = 0; j < 8; j++)
#pragma unroll
            for (int e = 0; e < 4; e++) {
                float v = sacc[j][e] * scale;
                if (need_mask) {
                    int col = k0 + j * 8 + 2 * c + (e & 1);
                    int row = q0 + qrow + ((e & 2) ? 8 : 0);
                    if (col > row) v = -1e30f;
                }
                sacc[j][e] = v;
            }

        // ---- online softmax ----
#pragma unroll
        for (int half = 0; half < 2; half++) {
            const int e0 = half * 2;
            float rmax = -1e30f;
#pragma unroll
            for (int j = 0; j < 8; j++)
                rmax = fmaxf(rmax, fmaxf(sacc[j][e0], sacc[j][e0 + 1]));
            rmax = fmaxf(rmax, __shfl_xor_sync(0xffffffffu, rmax, 1));
            rmax = fmaxf(rmax, __shfl_xor_sync(0xffffffffu, rmax, 2));
            float mnew = fmaxf(m_s[half], rmax);
            float corr = __expf(m_s[half] - mnew);
            float rsum = 0.f;
#pragma unroll
            for (int j = 0; j < 8; j++) {
                float p0 = __expf(sacc[j][e0] - mnew);
                float p1 = __expf(sacc[j][e0 + 1] - mnew);
                sacc[j][e0] = p0; sacc[j][e0 + 1] = p1;
                rsum += p0 + p1;
            }
            rsum += __shfl_xor_sync(0xffffffffu, rsum, 1);
            rsum += __shfl_xor_sync(0xffffffffu, rsum, 2);
            l_s[half] = l_s[half] * corr + rsum;
            m_s[half] = mnew;
#pragma unroll
            for (int j = 0; j < 16; j++) {
                O[j][e0]     *= corr;
                O[j][e0 + 1] *= corr;
            }
        }

        // ---- P -> smem (tf32-rounded) ----
#pragma unroll
        for (int j = 0; j < 8; j++) {
            int ck = 2 * j + (c >> 1);
            int off = swz(r, ck) * 4 + (c & 1) * 2;
            *(float2*)&Ps[qrow * 64 + off] =
                make_float2(rnd_tf32(sacc[j][0]), rnd_tf32(sacc[j][1]));
            *(float2*)&Ps[(qrow + 8) * 64 + off] =
                make_float2(rnd_tf32(sacc[j][2]), rnd_tf32(sacc[j][3]));
        }
        __syncwarp();

        // ---- O += P V ----
        const uint32_t* Pu = (const uint32_t*)Ps;
#pragma unroll
        for (int ks = 0; ks < 8; ks++) {
            const int ch0 = swz(r, 2 * ks) * 4;
            const int ch1 = swz(r, 2 * ks + 1) * 4;
            uint32_t a[4];
            a[0] = Pu[qrow * 64 + ch0 + c];
            a[1] = Pu[(qrow + 8) * 64 + ch0 + c];
            a[2] = Pu[qrow * 64 + ch1 + c];
            a[3] = Pu[(qrow + 8) * 64 + ch1 + c];
#pragma unroll
            for (int j = 0; j < 16; j++) {
                const int vrow = j * 8 + r;
                uint32_t b[2];
                b[0] = Vsb[vrow * 64 + ch0 + c];
                b[1] = Vsb[vrow * 64 + ch1 + c];
                mma_tf32(O[j], a, b);
            }
        }
        __syncthreads();
    }

    // ---- epilogue (tf32-rounded for the O-projection GEMM) ----
    const int b = bh >> 4, h = bh & 15;
    const float inv0 = 1.f / l_s[0];
    const float inv1 = 1.f / l_s[1];
    const int row0 = q0 + qrow, row1 = row0 + 8;
#pragma unroll
    for (int j = 0; j < 16; j++) {
        int n = h * HDIM + j * 8 + 2 * c;
        *(float2*)&g_attn[(size_t)(b * SEQ + row0) * HID + n] =
            make_float2(rnd_tf32(O[j][0] * inv0), rnd_tf32(O[j][1] * inv0));
        *(float2*)&g_attn[(size_t)(b * SEQ + row1) * HID + n] =
            make_float2(rnd_tf32(O[j][2] * inv1), rnd_tf32(O[j][3] * inv1));
    }
}

// ---------------------------------------------------------------------------
extern "C" void kernel_launch(void* const* d_in, const int* in_sizes, int n_in,
                              void* d_out, int out_size)
{
    const float* x  = (const float*)d_in[0];
    const float* Wq = (const float*)d_in[1];
    const float* bq = (const float*)d_in[2];
    const float* Wk = (const float*)d_in[3];
    const float* bk = (const float*)d_in[4];
    const float* Wv = (const float*)d_in[5];
    const float* bv = (const float*)d_in[6];
    const float* Wo = (const float*)d_in[7];
    const float* bo = (const float*)d_in[8];
    float* out = (float*)d_out;

    float *q, *k, *vt, *attn, *xr, *wr;
    cudaGetSymbolAddress((void**)&q,    g_Q);
    cudaGetSymbolAddress((void**)&k,    g_K);
    cudaGetSymbolAddress((void**)&vt,   g_Vt);
    cudaGetSymbolAddress((void**)&attn, g_attn);
    cudaGetSymbolAddress((void**)&xr,   g_xr);
    cudaGetSymbolAddress((void**)&wr,   g_Wr);

    const size_t gemm_smem = BUF_FLOATS * 2 * sizeof(float);        // 64 KB
    cudaFuncSetAttribute(gemm_tf32_kernel,
                         cudaFuncAttributeMaxDynamicSharedMemorySize, (int)gemm_smem);
    const size_t attn_smem = ATTN_SMEM_FLOATS * sizeof(float);      // 224 KB
    cudaFuncSetAttribute(attn_tc_kernel,
                         cudaFuncAttributeMaxDynamicSharedMemorySize, (int)attn_smem);

    const int NX4 = MROWS * HID / 4;   // 2,097,152
    const int NW4 = HID * HID / 4;     // 1,048,576
    float* wq_r = wr;
    float* wk_r = wr + (size_t)HID * HID;
    float* wv_r = wr + 2ull * HID * HID;
    float* wo_r = wr + 3ull * HID * HID;

    round_tf32_kernel<<<NX4 / 256, 256>>>(x,  xr,   NX4);
    round_tf32_kernel<<<NW4 / 256, 256>>>(Wq, wq_r, NW4);
    round_tf32_kernel<<<NW4 / 256, 256>>>(Wk, wk_r, NW4);
    round_tf32_kernel<<<NW4 / 256, 256>>>(Wv, wv_r, NW4);
    round_tf32_kernel<<<NW4 / 256, 256>>>(Wo, wo_r, NW4);

    dim3 gemm_grid(HID / 128, MROWS / 128); // (16, 32)
    gemm_tf32_kernel<<<gemm_grid, 256, gemm_smem>>>(xr, wq_r, bq, q, 2);
    gemm_tf32_kernel<<<gemm_grid, 256, gemm_smem>>>(xr, wk_r, bk, k, 2);
    gemm_tf32_kernel<<<gemm_grid, 256, gemm_smem>>>(xr, wv_r, bv, vt, 1);
    attn_tc_kernel<<<dim3(SEQ / 128, BH), 256, attn_smem>>>();
    gemm_tf32_kernel<<<gemm_grid, 256, gemm_smem>>>(attn, wo_r, bo, out, 0);
}

// round 6
// speedup vs baseline: 4.7709x; 1.0577x over previous
#include <cuda_runtime.h>
#include <cstdint>

#define HID   2048
#define MROWS 4096   // B*S
#define NHEAD 16
#define HDIM  128
#define SEQ   2048
#define BH    32     // B*NHEAD

// Scratch (no allocations allowed)
__device__ float g_Q [BH * SEQ * HDIM];       // [bh][s][d]   (tf32-rounded)
__device__ float g_K [BH * SEQ * HDIM];       // [bh][s][d]   (tf32-rounded)
__device__ float g_Vt[BH * HDIM * SEQ];       // [bh][d][s]   (tf32-rounded)
__device__ float g_attn[(size_t)MROWS * HID]; // [B*S][nh*hd] (tf32-rounded)
__device__ float g_xr[(size_t)MROWS * HID];   // rounded x
__device__ float g_Wr[4ull * HID * HID];      // rounded Wq,Wk,Wv,Wo (contiguous)
__device__ float g_bqkv[3 * HID];             // concat bq|bk|bv

// ---------------------------------------------------------------------------
// helpers
// ---------------------------------------------------------------------------
__device__ __forceinline__ void cp_async16(void* smem_dst, const void* gmem_src) {
    uint32_t s = (uint32_t)__cvta_generic_to_shared(smem_dst);
    asm volatile("cp.async.cg.shared.global [%0], [%1], 16;\n" :: "r"(s), "l"(gmem_src));
}
__device__ __forceinline__ float rnd_tf32(float f) {
    uint32_t u;
    asm("cvt.rna.tf32.f32 %0, %1;" : "=r"(u) : "f"(f));
    return __uint_as_float(u);
}
__device__ __forceinline__ void mma_tf32(float* d, const uint32_t* a, const uint32_t* b) {
    asm volatile(
        "mma.sync.aligned.m16n8k8.row.col.f32.tf32.tf32.f32 "
        "{%0,%1,%2,%3}, {%4,%5,%6,%7}, {%8,%9}, {%0,%1,%2,%3};"
        : "+f"(d[0]), "+f"(d[1]), "+f"(d[2]), "+f"(d[3])
        : "r"(a[0]), "r"(a[1]), "r"(a[2]), "r"(a[3]), "r"(b[0]), "r"(b[1]));
}
__device__ __forceinline__ int swz(int row, int ck) {
    return (ck & ~7) | ((ck ^ row) & 7);
}

// ---------------------------------------------------------------------------
// elementwise tf32 pre-round kernels
// ---------------------------------------------------------------------------
__global__ __launch_bounds__(256)
void round_tf32_kernel(const float* __restrict__ in, float* __restrict__ out, int n4)
{
    int i = blockIdx.x * blockDim.x + threadIdx.x;
    if (i < n4) {
        float4 v = ((const float4*)in)[i];
        v.x = rnd_tf32(v.x); v.y = rnd_tf32(v.y);
        v.z = rnd_tf32(v.z); v.w = rnd_tf32(v.w);
        ((float4*)out)[i] = v;
    }
}

__global__ __launch_bounds__(256)
void round_w4_kernel(const float* __restrict__ w0, const float* __restrict__ w1,
                     const float* __restrict__ w2, const float* __restrict__ w3,
                     float* __restrict__ out, int n4each)
{
    int i = blockIdx.x * blockDim.x + threadIdx.x;
    int which = i / n4each;
    int j = i - which * n4each;
    const float* src = (which == 0) ? w0 : (which == 1) ? w1 : (which == 2) ? w2 : w3;
    float4 v = ((const float4*)src)[j];
    v.x = rnd_tf32(v.x); v.y = rnd_tf32(v.y);
    v.z = rnd_tf32(v.z); v.w = rnd_tf32(v.w);
    ((float4*)out)[i] = v;
}

__global__ __launch_bounds__(256)
void concat_bias_kernel(const float* __restrict__ bq, const float* __restrict__ bk,
                        const float* __restrict__ bv, float* __restrict__ out)
{
    int i = blockIdx.x * blockDim.x + threadIdx.x; // 0..6143
    const float* s = (i < HID) ? bq : (i < 2 * HID) ? bk : bv;
    out[i] = s[i & (HID - 1)];
}

// ---------------------------------------------------------------------------
// Merged QKV tf32 GEMM (warp MMA, raw-bit operands; inputs pre-rounded).
// C[m,n] = sum_k A[m,k]*Wcat[n,k] + bcat[n],  n in [0,6144)
// Routes to g_Q/g_K ([bh][s][d]) for n<4096, g_Vt ([bh][d][s]) for n>=4096.
// ---------------------------------------------------------------------------
#define BK 32
#define NKT (HID / BK)   // 64
#define BUF_FLOATS 8192

__global__ __launch_bounds__(256, 2)
void gemm_qkv_kernel(const float* __restrict__ A,
                     const float* __restrict__ Wcat,
                     float* __restrict__ qout,
                     float* __restrict__ kout,
                     float* __restrict__ vout)
{
    extern __shared__ float sm[];
    const int t    = threadIdx.x;
    const int lane = t & 31;
    const int wid  = t >> 5;
    const int wm   = wid & 3;
    const int wn   = wid >> 2;
    const int m0   = blockIdx.y * 128;
    const int n0g  = blockIdx.x * 128;         // global n within 6144
    const int mat  = blockIdx.x >> 4;          // 0=Q 1=K 2=V
    const int r = lane >> 2;
    const int c = lane & 3;

    float acc[2][8][4];
#pragma unroll
    for (int i = 0; i < 2; i++)
#pragma unroll
        for (int j = 0; j < 8; j++)
#pragma unroll
            for (int e = 0; e < 4; e++) acc[i][j][e] = 0.f;

    auto issue_tile = [&](int kt, int buf) {
        float* As = sm + buf * BUF_FLOATS;
        float* Ws = As + 4096;
        const int k0 = kt * BK;
#pragma unroll
        for (int i = 0; i < 4; i++) {
            int id  = t + i * 256;
            int row = id >> 3;
            int ck  = id & 7;
            int swk = (ck ^ (row & 7)) << 2;
            cp_async16(As + row * 32 + swk,
                       A + (size_t)(m0 + row) * HID + k0 + ck * 4);
            cp_async16(Ws + row * 32 + swk,
                       Wcat + (size_t)(n0g + row) * HID + k0 + ck * 4);
        }
        asm volatile("cp.async.commit_group;\n");
    };

    issue_tile(0, 0);

    for (int kt = 0; kt < NKT; kt++) {
        if (kt + 1 < NKT) {
            issue_tile(kt + 1, (kt + 1) & 1);
            asm volatile("cp.async.wait_group 1;\n");
        } else {
            asm volatile("cp.async.wait_group 0;\n");
        }
        __syncthreads();

        const uint32_t* As = (const uint32_t*)(sm + (kt & 1) * BUF_FLOATS);
        const uint32_t* Ws = As + 4096;

#pragma unroll
        for (int ks = 0; ks < 4; ks++) {
            const int ch0 = ((2 * ks) ^ r) << 2;
            const int ch1 = ((2 * ks + 1) ^ r) << 2;
            uint32_t af[2][4];
#pragma unroll
            for (int i = 0; i < 2; i++) {
                int mrow = wm * 32 + i * 16 + r;
                af[i][0] = As[mrow * 32 + ch0 + c];
                af[i][1] = As[(mrow + 8) * 32 + ch0 + c];
                af[i][2] = As[mrow * 32 + ch1 + c];
                af[i][3] = As[(mrow + 8) * 32 + ch1 + c];
            }
            uint32_t bf[8][2];
#pragma unroll
            for (int j = 0; j < 8; j++) {
                int nrow = wn * 64 + j * 8 + r;
                bf[j][0] = Ws[nrow * 32 + ch0 + c];
                bf[j][1] = Ws[nrow * 32 + ch1 + c];
            }
#pragma unroll
            for (int i = 0; i < 2; i++)
#pragma unroll
                for (int j = 0; j < 8; j++)
                    mma_tf32(acc[i][j], af[i], bf[j]);
        }
        __syncthreads();
    }

    float* outQK = (mat == 0) ? qout : kout;

#pragma unroll
    for (int i = 0; i < 2; i++) {
        int r0 = m0 + wm * 32 + i * 16 + r;
        int r1 = r0 + 8;
        int b_0 = r0 >> 11, s_0 = r0 & 2047;
        int b_1 = r1 >> 11, s_1 = r1 & 2047;
#pragma unroll
        for (int j = 0; j < 8; j++) {
            int nbg = n0g + wn * 64 + j * 8 + 2 * c;   // global (bias)
            int nb  = nbg & 2047;                      // within matrix
            float b0 = g_bqkv[nbg], b1 = g_bqkv[nbg + 1];
            float d00 = rnd_tf32(acc[i][j][0] + b0);
            float d01 = rnd_tf32(acc[i][j][1] + b1);
            float d10 = rnd_tf32(acc[i][j][2] + b0);
            float d11 = rnd_tf32(acc[i][j][3] + b1);
            int h = nb >> 7, d = nb & 127;
            if (mat < 2) {
                *(float2*)&outQK[(size_t)((b_0 * NHEAD + h) * SEQ + s_0) * HDIM + d] =
                    make_float2(d00, d01);
                *(float2*)&outQK[(size_t)((b_1 * NHEAD + h) * SEQ + s_1) * HDIM + d] =
                    make_float2(d10, d11);
            } else {
                size_t base0 = (size_t)((b_0 * NHEAD + h) * HDIM + d) * SEQ;
                size_t base1 = (size_t)((b_1 * NHEAD + h) * HDIM + d) * SEQ;
                vout[base0 + s_0]       = d00;
                vout[base0 + SEQ + s_0] = d01;
                vout[base1 + s_1]       = d10;
                vout[base1 + SEQ + s_1] = d11;
            }
        }
    }
}

// ---------------------------------------------------------------------------
// O-projection GEMM (row-major fp32 out)
// ---------------------------------------------------------------------------
__global__ __launch_bounds__(256, 2)
void gemm_o_kernel(const float* __restrict__ A,
                   const float* __restrict__ W,
                   const float* __restrict__ bias,
                   float* __restrict__ out)
{
    extern __shared__ float sm[];
    const int t    = threadIdx.x;
    const int lane = t & 31;
    const int wid  = t >> 5;
    const int wm   = wid & 3;
    const int wn   = wid >> 2;
    const int m0   = blockIdx.y * 128;
    const int n0   = blockIdx.x * 128;
    const int r = lane >> 2;
    const int c = lane & 3;

    float acc[2][8][4];
#pragma unroll
    for (int i = 0; i < 2; i++)
#pragma unroll
        for (int j = 0; j < 8; j++)
#pragma unroll
            for (int e = 0; e < 4; e++) acc[i][j][e] = 0.f;

    auto issue_tile = [&](int kt, int buf) {
        float* As = sm + buf * BUF_FLOATS;
        float* Ws = As + 4096;
        const int k0 = kt * BK;
#pragma unroll
        for (int i = 0; i < 4; i++) {
            int id  = t + i * 256;
            int row = id >> 3;
            int ck  = id & 7;
            int swk = (ck ^ (row & 7)) << 2;
            cp_async16(As + row * 32 + swk,
                       A + (size_t)(m0 + row) * HID + k0 + ck * 4);
            cp_async16(Ws + row * 32 + swk,
                       W + (size_t)(n0 + row) * HID + k0 + ck * 4);
        }
        asm volatile("cp.async.commit_group;\n");
    };

    issue_tile(0, 0);

    for (int kt = 0; kt < NKT; kt++) {
        if (kt + 1 < NKT) {
            issue_tile(kt + 1, (kt + 1) & 1);
            asm volatile("cp.async.wait_group 1;\n");
        } else {
            asm volatile("cp.async.wait_group 0;\n");
        }
        __syncthreads();

        const uint32_t* As = (const uint32_t*)(sm + (kt & 1) * BUF_FLOATS);
        const uint32_t* Ws = As + 4096;

#pragma unroll
        for (int ks = 0; ks < 4; ks++) {
            const int ch0 = ((2 * ks) ^ r) << 2;
            const int ch1 = ((2 * ks + 1) ^ r) << 2;
            uint32_t af[2][4];
#pragma unroll
            for (int i = 0; i < 2; i++) {
                int mrow = wm * 32 + i * 16 + r;
                af[i][0] = As[mrow * 32 + ch0 + c];
                af[i][1] = As[(mrow + 8) * 32 + ch0 + c];
                af[i][2] = As[mrow * 32 + ch1 + c];
                af[i][3] = As[(mrow + 8) * 32 + ch1 + c];
            }
            uint32_t bf[8][2];
#pragma unroll
            for (int j = 0; j < 8; j++) {
                int nrow = wn * 64 + j * 8 + r;
                bf[j][0] = Ws[nrow * 32 + ch0 + c];
                bf[j][1] = Ws[nrow * 32 + ch1 + c];
            }
#pragma unroll
            for (int i = 0; i < 2; i++)
#pragma unroll
                for (int j = 0; j < 8; j++)
                    mma_tf32(acc[i][j], af[i], bf[j]);
        }
        __syncthreads();
    }

#pragma unroll
    for (int i = 0; i < 2; i++) {
        int r0 = m0 + wm * 32 + i * 16 + r;
        int r1 = r0 + 8;
#pragma unroll
        for (int j = 0; j < 8; j++) {
            int nb = n0 + wn * 64 + j * 8 + 2 * c;
            float b0 = bias[nb], b1 = bias[nb + 1];
            *(float2*)&out[(size_t)r0 * HID + nb] =
                make_float2(acc[i][j][0] + b0, acc[i][j][1] + b1);
            *(float2*)&out[(size_t)r1 * HID + nb] =
                make_float2(acc[i][j][2] + b0, acc[i][j][3] + b1);
        }
    }
}

// ---------------------------------------------------------------------------
// Tensor-core flash attention (causal, tf32 warp MMA) — unchanged from r4.
// smem (floats): Qs 16384 | Ks 2x8192 | Vs 2x8192 | Ps 8192 = 224KB
// ---------------------------------------------------------------------------
#define QS_OFF 0
#define KS_OFF 16384
#define VS_OFF 32768
#define PS_OFF 49152
#define ATTN_SMEM_FLOATS 57344

__global__ __launch_bounds__(256, 1)
void attn_tc_kernel()
{
    extern __shared__ float sm[];
    const uint32_t* Qs = (const uint32_t*)(sm + QS_OFF);
    float* Ps = sm + PS_OFF;

    const int t    = threadIdx.x;
    const int lane = t & 31;
    const int w    = t >> 5;
    const int r    = lane >> 2;
    const int c    = lane & 3;
    const int qbI  = 15 - blockIdx.x;
    const int bh   = blockIdx.y;
    const int q0   = qbI * 128;
    const int nkb  = 2 * qbI + 2;
    const float scale = 0.08838834764831845f; // 1/sqrt(128)

    const float* Qg = g_Q  + (size_t)bh * SEQ * HDIM;
    const float* Kg = g_K  + (size_t)bh * SEQ * HDIM;
    const float* Vg = g_Vt + (size_t)bh * HDIM * SEQ;

    auto issueKV = [&](int kb, int buf) {
        float* Ksb = sm + KS_OFF + buf * 8192;
        float* Vsb = sm + VS_OFF + buf * 8192;
        const int k0 = kb * 64;
#pragma unroll
        for (int i = 0; i < 8; i++) {
            int id = t + i * 256;
            int row = id >> 5, ck = id & 31;
            cp_async16(Ksb + row * 128 + swz(row & 7, ck) * 4,
                       Kg + (size_t)(k0 + row) * HDIM + ck * 4);
        }
#pragma unroll
        for (int i = 0; i < 8; i++) {
            int id = t + i * 256;
            int row = id >> 4, ck = id & 15;
            cp_async16(Vsb + row * 64 + swz(row & 7, ck) * 4,
                       Vg + (size_t)row * SEQ + k0 + ck * 4);
        }
        asm volatile("cp.async.commit_group;\n");
    };

#pragma unroll
    for (int i = 0; i < 16; i++) {
        int id = t + i * 256;
        int row = id >> 5, ck = id & 31;
        cp_async16((float*)Qs + row * 128 + swz(row & 7, ck) * 4,
                   Qg + (size_t)(q0 + row) * HDIM + ck * 4);
    }
    issueKV(0, 0);

    float m_s[2], l_s[2], O[16][4];
#pragma unroll
    for (int e = 0; e < 2; e++) { m_s[e] = -1e30f; l_s[e] = 0.f; }
#pragma unroll
    for (int j = 0; j < 16; j++)
#pragma unroll
        for (int e = 0; e < 4; e++) O[j][e] = 0.f;

    const int qrow = w * 16 + r;

    for (int kb = 0; kb < nkb; kb++) {
        const int buf = kb & 1;
        const int k0  = kb * 64;
        if (kb + 1 < nkb) {
            issueKV(kb + 1, (kb + 1) & 1);
            asm volatile("cp.async.wait_group 1;\n");
        } else {
            asm volatile("cp.async.wait_group 0;\n");
        }
        __syncthreads();

        const uint32_t* Ksb = (const uint32_t*)(sm + KS_OFF + buf * 8192);
        const uint32_t* Vsb = (const uint32_t*)(sm + VS_OFF + buf * 8192);

        float sacc[8][4];
#pragma unroll
        for (int j = 0; j < 8; j++)
#pragma unroll
            for (int e = 0; e < 4; e++) sacc[j][e] = 0.f;

#pragma unroll
        for (int ks = 0; ks < 16; ks++) {
            const int ch0 = swz(r, 2 * ks) * 4;
            const int ch1 = swz(r, 2 * ks + 1) * 4;
            uint32_t a[4];
            a[0] = Qs[qrow * 128 + ch0 + c];
            a[1] = Qs[(qrow + 8) * 128 + ch0 + c];
            a[2] = Qs[qrow * 128 + ch1 + c];
            a[3] = Qs[(qrow + 8) * 128 + ch1 + c];
#pragma unroll
            for (int j = 0; j < 8; j++) {
                const int krow = j * 8 + r;
                uint32_t b[2];
                b[0] = Ksb[krow * 128 + ch0 + c];
                b[1] = Ksb[krow * 128 + ch1 + c];
                mma_tf32(sacc[j], a, b);
            }
        }

        const bool need_mask = (k0 + 63 > q0);
#pragma unroll
        for (int j = 0; j < 8; j++)
#pragma unroll
            for (int e = 0; e < 4; e++) {
                float v = sacc[j][e] * scale;
                if (need_mask) {
                    int col = k0 + j * 8 + 2 * c + (e & 1);
                    int row = q0 + qrow + ((e & 2) ? 8 : 0);
                    if (col > row) v = -1e30f;
                }
                sacc[j][e] = v;
            }

#pragma unroll
        for (int half = 0; half < 2; half++) {
            const int e0 = half * 2;
            float rmax = -1e30f;
#pragma unroll
            for (int j = 0; j < 8; j++)
                rmax = fmaxf(rmax, fmaxf(sacc[j][e0], sacc[j][e0 + 1]));
            rmax = fmaxf(rmax, __shfl_xor_sync(0xffffffffu, rmax, 1));
            rmax = fmaxf(rmax, __shfl_xor_sync(0xffffffffu, rmax, 2));
            float mnew = fmaxf(m_s[half], rmax);
            float corr = __expf(m_s[half] - mnew);
            float rsum = 0.f;
#pragma unroll
            for (int j = 0; j < 8; j++) {
                float p0 = __expf(sacc[j][e0] - mnew);
                float p1 = __expf(sacc[j][e0 + 1] - mnew);
                sacc[j][e0] = p0; sacc[j][e0 + 1] = p1;
                rsum += p0 + p1;
            }
            rsum += __shfl_xor_sync(0xffffffffu, rsum, 1);
            rsum += __shfl_xor_sync(0xffffffffu, rsum, 2);
            l_s[half] = l_s[half] * corr + rsum;
            m_s[half] = mnew;
#pragma unroll
            for (int j = 0; j < 16; j++) {
                O[j][e0]     *= corr;
                O[j][e0 + 1] *= corr;
            }
        }

#pragma unroll
        for (int j = 0; j < 8; j++) {
            int ck = 2 * j + (c >> 1);
            int off = swz(r, ck) * 4 + (c & 1) * 2;
            *(float2*)&Ps[qrow * 64 + off] =
                make_float2(rnd_tf32(sacc[j][0]), rnd_tf32(sacc[j][1]));
            *(float2*)&Ps[(qrow + 8) * 64 + off] =
                make_float2(rnd_tf32(sacc[j][2]), rnd_tf32(sacc[j][3]));
        }
        __syncwarp();

        const uint32_t* Pu = (const uint32_t*)Ps;
#pragma unroll
        for (int ks = 0; ks < 8; ks++) {
            const int ch0 = swz(r, 2 * ks) * 4;
            const int ch1 = swz(r, 2 * ks + 1) * 4;
            uint32_t a[4];
            a[0] = Pu[qrow * 64 + ch0 + c];
            a[1] = Pu[(qrow + 8) * 64 + ch0 + c];
            a[2] = Pu[qrow * 64 + ch1 + c];
            a[3] = Pu[(qrow + 8) * 64 + ch1 + c];
#pragma unroll
            for (int j = 0; j < 16; j++) {
                const int vrow = j * 8 + r;
                uint32_t b[2];
                b[0] = Vsb[vrow * 64 + ch0 + c];
                b[1] = Vsb[vrow * 64 + ch1 + c];
                mma_tf32(O[j], a, b);
            }
        }
        __syncthreads();
    }

    const int b = bh >> 4, h = bh & 15;
    const float inv0 = 1.f / l_s[0];
    const float inv1 = 1.f / l_s[1];
    const int row0 = q0 + qrow, row1 = row0 + 8;
#pragma unroll
    for (int j = 0; j < 16; j++) {
        int n = h * HDIM + j * 8 + 2 * c;
        *(float2*)&g_attn[(size_t)(b * SEQ + row0) * HID + n] =
            make_float2(rnd_tf32(O[j][0] * inv0), rnd_tf32(O[j][1] * inv0));
        *(float2*)&g_attn[(size_t)(b * SEQ + row1) * HID + n] =
            make_float2(rnd_tf32(O[j][2] * inv1), rnd_tf32(O[j][3] * inv1));
    }
}

// ---------------------------------------------------------------------------
extern "C" void kernel_launch(void* const* d_in, const int* in_sizes, int n_in,
                              void* d_out, int out_size)
{
    const float* x  = (const float*)d_in[0];
    const float* Wq = (const float*)d_in[1];
    const float* bq = (const float*)d_in[2];
    const float* Wk = (const float*)d_in[3];
    const float* bk = (const float*)d_in[4];
    const float* Wv = (const float*)d_in[5];
    const float* bv = (const float*)d_in[6];
    const float* Wo = (const float*)d_in[7];
    const float* bo = (const float*)d_in[8];
    float* out = (float*)d_out;

    float *q, *k, *vt, *attn, *xr, *wr, *bcat;
    cudaGetSymbolAddress((void**)&q,    g_Q);
    cudaGetSymbolAddress((void**)&k,    g_K);
    cudaGetSymbolAddress((void**)&vt,   g_Vt);
    cudaGetSymbolAddress((void**)&attn, g_attn);
    cudaGetSymbolAddress((void**)&xr,   g_xr);
    cudaGetSymbolAddress((void**)&wr,   g_Wr);
    cudaGetSymbolAddress((void**)&bcat, g_bqkv);

    const size_t gemm_smem = BUF_FLOATS * 2 * sizeof(float);        // 64 KB
    cudaFuncSetAttribute(gemm_qkv_kernel,
                         cudaFuncAttributeMaxDynamicSharedMemorySize, (int)gemm_smem);
    cudaFuncSetAttribute(gemm_o_kernel,
                         cudaFuncAttributeMaxDynamicSharedMemorySize, (int)gemm_smem);
    const size_t attn_smem = ATTN_SMEM_FLOATS * sizeof(float);      // 224 KB
    cudaFuncSetAttribute(attn_tc_kernel,
                         cudaFuncAttributeMaxDynamicSharedMemorySize, (int)attn_smem);

    const int NX4 = MROWS * HID / 4;   // 2,097,152
    const int NW4 = HID * HID / 4;     // 1,048,576
    float* wo_r = wr + 3ull * HID * HID;

    round_tf32_kernel<<<NX4 / 256, 256>>>(x, xr, NX4);
    round_w4_kernel<<<4 * NW4 / 256, 256>>>(Wq, Wk, Wv, Wo, wr, NW4);
    concat_bias_kernel<<<3 * HID / 256, 256>>>(bq, bk, bv, bcat);

    gemm_qkv_kernel<<<dim3(3 * HID / 128, MROWS / 128), 256, gemm_smem>>>(
        xr, wr, q, k, vt);                       // grid (48, 32)
    attn_tc_kernel<<<dim3(SEQ / 128, BH), 256, attn_smem>>>();
    gemm_o_kernel<<<dim3(HID / 128, MROWS / 128), 256, gemm_smem>>>(
        attn, wo_r, bo, out);                    // grid (16, 32)
}

// round 7
// speedup vs baseline: 5.2459x; 1.0996x over previous
#include <cuda_runtime.h>
#include <cstdint>

#define HID   2048
#define MROWS 4096   // B*S
#define NHEAD 16
#define HDIM  128
#define SEQ   2048
#define BH    32     // B*NHEAD

// Scratch (no allocations allowed)
__device__ float g_Q [BH * SEQ * HDIM];       // [bh][s][d]   (tf32-rounded)
__device__ float g_K [BH * SEQ * HDIM];       // [bh][s][d]   (tf32-rounded)
__device__ float g_Vt[BH * HDIM * SEQ];       // [bh][d][s]   (tf32-rounded)
__device__ float g_attn[(size_t)MROWS * HID]; // [B*S][nh*hd] (tf32-rounded)
__device__ float g_xr[(size_t)MROWS * HID];   // rounded x
__device__ float g_Wr[4ull * HID * HID];      // rounded Wq,Wk,Wv,Wo (contiguous)
__device__ float g_bqkv[3 * HID];             // concat bq|bk|bv

// ---------------------------------------------------------------------------
// helpers
// ---------------------------------------------------------------------------
__device__ __forceinline__ void cp_async16(void* smem_dst, const void* gmem_src) {
    uint32_t s = (uint32_t)__cvta_generic_to_shared(smem_dst);
    asm volatile("cp.async.cg.shared.global [%0], [%1], 16;\n" :: "r"(s), "l"(gmem_src));
}
__device__ __forceinline__ float rnd_tf32(float f) {
    uint32_t u;
    asm("cvt.rna.tf32.f32 %0, %1;" : "=r"(u) : "f"(f));
    return __uint_as_float(u);
}
__device__ __forceinline__ void mma_tf32(float* d, const uint32_t* a, const uint32_t* b) {
    asm volatile(
        "mma.sync.aligned.m16n8k8.row.col.f32.tf32.tf32.f32 "
        "{%0,%1,%2,%3}, {%4,%5,%6,%7}, {%8,%9}, {%0,%1,%2,%3};"
        : "+f"(d[0]), "+f"(d[1]), "+f"(d[2]), "+f"(d[3])
        : "r"(a[0]), "r"(a[1]), "r"(a[2]), "r"(a[3]), "r"(b[0]), "r"(b[1]));
}
__device__ __forceinline__ void ldsm4(uint32_t* d, uint32_t addr) {
    asm volatile("ldmatrix.sync.aligned.m8n8.x4.shared.b16 {%0,%1,%2,%3}, [%4];"
        : "=r"(d[0]), "=r"(d[1]), "=r"(d[2]), "=r"(d[3]) : "r"(addr));
}
__device__ __forceinline__ int swz(int row, int ck) {
    return (ck & ~7) | ((ck ^ row) & 7);
}
__device__ __forceinline__ uint32_t smem_u32(const void* p) {
    return (uint32_t)__cvta_generic_to_shared(p);
}

// ---------------------------------------------------------------------------
// elementwise tf32 pre-round kernels
// ---------------------------------------------------------------------------
__global__ __launch_bounds__(256)
void round_tf32_kernel(const float* __restrict__ in, float* __restrict__ out, int n4)
{
    int i = blockIdx.x * blockDim.x + threadIdx.x;
    if (i < n4) {
        float4 v = ((const float4*)in)[i];
        v.x = rnd_tf32(v.x); v.y = rnd_tf32(v.y);
        v.z = rnd_tf32(v.z); v.w = rnd_tf32(v.w);
        ((float4*)out)[i] = v;
    }
}

__global__ __launch_bounds__(256)
void round_w4_kernel(const float* __restrict__ w0, const float* __restrict__ w1,
                     const float* __restrict__ w2, const float* __restrict__ w3,
                     float* __restrict__ out, int n4each)
{
    int i = blockIdx.x * blockDim.x + threadIdx.x;
    int which = i / n4each;
    int j = i - which * n4each;
    const float* src = (which == 0) ? w0 : (which == 1) ? w1 : (which == 2) ? w2 : w3;
    float4 v = ((const float4*)src)[j];
    v.x = rnd_tf32(v.x); v.y = rnd_tf32(v.y);
    v.z = rnd_tf32(v.z); v.w = rnd_tf32(v.w);
    ((float4*)out)[i] = v;
}

__global__ __launch_bounds__(256)
void concat_bias_kernel(const float* __restrict__ bq, const float* __restrict__ bk,
                        const float* __restrict__ bv, float* __restrict__ out)
{
    int i = blockIdx.x * blockDim.x + threadIdx.x; // 0..6143
    const float* s = (i < HID) ? bq : (i < 2 * HID) ? bk : bv;
    out[i] = s[i & (HID - 1)];
}

// ---------------------------------------------------------------------------
// Merged QKV tf32 GEMM, LDSM fragment loads.
// ---------------------------------------------------------------------------
#define BK 32
#define NKT (HID / BK)   // 64
#define BUF_FLOATS 8192

__global__ __launch_bounds__(256, 2)
void gemm_qkv_kernel(const float* __restrict__ A,
                     const float* __restrict__ Wcat,
                     float* __restrict__ qout,
                     float* __restrict__ kout,
                     float* __restrict__ vout)
{
    extern __shared__ float sm[];
    const int t    = threadIdx.x;
    const int lane = t & 31;
    const int wid  = t >> 5;
    const int wm   = wid & 3;
    const int wn   = wid >> 2;
    const int m0   = blockIdx.y * 128;
    const int n0g  = blockIdx.x * 128;
    const int mat  = blockIdx.x >> 4;          // 0=Q 1=K 2=V
    const int r = lane >> 2;
    const int c = lane & 3;

    // ldmatrix lane geometry
    const int lane7 = lane & 7;
    const int a_sel = (lane >> 4) & 1;          // chunk parity for A
    const int a_i16 = ((lane >> 3) & 1) * 8;    // +8 rows
    const int b_sel = (lane >> 3) & 1;          // chunk parity for B
    const int b_n8  = ((lane >> 4) & 1) * 8;    // +8 n

    const int a_ro0 = (wm * 32 + a_i16 + lane7) * 128;        // bytes
    const int a_ro1 = a_ro0 + 16 * 128;
    int b_ro[4];
#pragma unroll
    for (int jp = 0; jp < 4; jp++)
        b_ro[jp] = (wn * 64 + jp * 16 + b_n8 + lane7) * 128;

    float acc[2][8][4];
#pragma unroll
    for (int i = 0; i < 2; i++)
#pragma unroll
        for (int j = 0; j < 8; j++)
#pragma unroll
            for (int e = 0; e < 4; e++) acc[i][j][e] = 0.f;

    auto issue_tile = [&](int kt, int buf) {
        float* As = sm + buf * BUF_FLOATS;
        float* Ws = As + 4096;
        const int k0 = kt * BK;
#pragma unroll
        for (int i = 0; i < 4; i++) {
            int id  = t + i * 256;
            int row = id >> 3;
            int ck  = id & 7;
            int swk = (ck ^ (row & 7)) << 2;
            cp_async16(As + row * 32 + swk,
                       A + (size_t)(m0 + row) * HID + k0 + ck * 4);
            cp_async16(Ws + row * 32 + swk,
                       Wcat + (size_t)(n0g + row) * HID + k0 + ck * 4);
        }
        asm volatile("cp.async.commit_group;\n");
    };

    issue_tile(0, 0);
    const uint32_t smbase = smem_u32(sm);

    for (int kt = 0; kt < NKT; kt++) {
        if (kt + 1 < NKT) {
            issue_tile(kt + 1, (kt + 1) & 1);
            asm volatile("cp.async.wait_group 1;\n");
        } else {
            asm volatile("cp.async.wait_group 0;\n");
        }
        __syncthreads();

        const uint32_t smA = smbase + (kt & 1) * (BUF_FLOATS * 4);
        const uint32_t smB = smA + 16384;

#pragma unroll
        for (int ks = 0; ks < 4; ks++) {
            const int ea = (((2 * ks + a_sel) ^ lane7) << 4);
            const int eb = (((2 * ks + b_sel) ^ lane7) << 4);
            uint32_t af0[4], af1[4];
            ldsm4(af0, smA + a_ro0 + ea);
            ldsm4(af1, smA + a_ro1 + ea);
#pragma unroll
            for (int jp = 0; jp < 4; jp++) {
                uint32_t bf[4];
                ldsm4(bf, smB + b_ro[jp] + eb);
                mma_tf32(acc[0][2 * jp],     af0, &bf[0]);
                mma_tf32(acc[0][2 * jp + 1], af0, &bf[2]);
                mma_tf32(acc[1][2 * jp],     af1, &bf[0]);
                mma_tf32(acc[1][2 * jp + 1], af1, &bf[2]);
            }
        }
        __syncthreads();
    }

    float* outQK = (mat == 0) ? qout : kout;

#pragma unroll
    for (int i = 0; i < 2; i++) {
        int r0 = m0 + wm * 32 + i * 16 + r;
        int r1 = r0 + 8;
        int b_0 = r0 >> 11, s_0 = r0 & 2047;
        int b_1 = r1 >> 11, s_1 = r1 & 2047;
#pragma unroll
        for (int j = 0; j < 8; j++) {
            int nbg = n0g + wn * 64 + j * 8 + 2 * c;
            int nb  = nbg & 2047;
            float b0 = g_bqkv[nbg], b1 = g_bqkv[nbg + 1];
            float d00 = rnd_tf32(acc[i][j][0] + b0);
            float d01 = rnd_tf32(acc[i][j][1] + b1);
            float d10 = rnd_tf32(acc[i][j][2] + b0);
            float d11 = rnd_tf32(acc[i][j][3] + b1);
            int h = nb >> 7, d = nb & 127;
            if (mat < 2) {
                *(float2*)&outQK[(size_t)((b_0 * NHEAD + h) * SEQ + s_0) * HDIM + d] =
                    make_float2(d00, d01);
                *(float2*)&outQK[(size_t)((b_1 * NHEAD + h) * SEQ + s_1) * HDIM + d] =
                    make_float2(d10, d11);
            } else {
                size_t base0 = (size_t)((b_0 * NHEAD + h) * HDIM + d) * SEQ;
                size_t base1 = (size_t)((b_1 * NHEAD + h) * HDIM + d) * SEQ;
                vout[base0 + s_0]       = d00;
                vout[base0 + SEQ + s_0] = d01;
                vout[base1 + s_1]       = d10;
                vout[base1 + SEQ + s_1] = d11;
            }
        }
    }
}

// ---------------------------------------------------------------------------
// O-projection GEMM (row-major fp32 out), LDSM fragment loads.
// ---------------------------------------------------------------------------
__global__ __launch_bounds__(256, 2)
void gemm_o_kernel(const float* __restrict__ A,
                   const float* __restrict__ W,
                   const float* __restrict__ bias,
                   float* __restrict__ out)
{
    extern __shared__ float sm[];
    const int t    = threadIdx.x;
    const int lane = t & 31;
    const int wid  = t >> 5;
    const int wm   = wid & 3;
    const int wn   = wid >> 2;
    const int m0   = blockIdx.y * 128;
    const int n0   = blockIdx.x * 128;
    const int r = lane >> 2;
    const int c = lane & 3;

    const int lane7 = lane & 7;
    const int a_sel = (lane >> 4) & 1;
    const int a_i16 = ((lane >> 3) & 1) * 8;
    const int b_sel = (lane >> 3) & 1;
    const int b_n8  = ((lane >> 4) & 1) * 8;

    const int a_ro0 = (wm * 32 + a_i16 + lane7) * 128;
    const int a_ro1 = a_ro0 + 16 * 128;
    int b_ro[4];
#pragma unroll
    for (int jp = 0; jp < 4; jp++)
        b_ro[jp] = (wn * 64 + jp * 16 + b_n8 + lane7) * 128;

    float acc[2][8][4];
#pragma unroll
    for (int i = 0; i < 2; i++)
#pragma unroll
        for (int j = 0; j < 8; j++)
#pragma unroll
            for (int e = 0; e < 4; e++) acc[i][j][e] = 0.f;

    auto issue_tile = [&](int kt, int buf) {
        float* As = sm + buf * BUF_FLOATS;
        float* Ws = As + 4096;
        const int k0 = kt * BK;
#pragma unroll
        for (int i = 0; i < 4; i++) {
            int id  = t + i * 256;
            int row = id >> 3;
            int ck  = id & 7;
            int swk = (ck ^ (row & 7)) << 2;
            cp_async16(As + row * 32 + swk,
                       A + (size_t)(m0 + row) * HID + k0 + ck * 4);
            cp_async16(Ws + row * 32 + swk,
                       W + (size_t)(n0 + row) * HID + k0 + ck * 4);
        }
        asm volatile("cp.async.commit_group;\n");
    };

    issue_tile(0, 0);
    const uint32_t smbase = smem_u32(sm);

    for (int kt = 0; kt < NKT; kt++) {
        if (kt + 1 < NKT) {
            issue_tile(kt + 1, (kt + 1) & 1);
            asm volatile("cp.async.wait_group 1;\n");
        } else {
            asm volatile("cp.async.wait_group 0;\n");
        }
        __syncthreads();

        const uint32_t smA = smbase + (kt & 1) * (BUF_FLOATS * 4);
        const uint32_t smB = smA + 16384;

#pragma unroll
        for (int ks = 0; ks < 4; ks++) {
            const int ea = (((2 * ks + a_sel) ^ lane7) << 4);
            const int eb = (((2 * ks + b_sel) ^ lane7) << 4);
            uint32_t af0[4], af1[4];
            ldsm4(af0, smA + a_ro0 + ea);
            ldsm4(af1, smA + a_ro1 + ea);
#pragma unroll
            for (int jp = 0; jp < 4; jp++) {
                uint32_t bf[4];
                ldsm4(bf, smB + b_ro[jp] + eb);
                mma_tf32(acc[0][2 * jp],     af0, &bf[0]);
                mma_tf32(acc[0][2 * jp + 1], af0, &bf[2]);
                mma_tf32(acc[1][2 * jp],     af1, &bf[0]);
                mma_tf32(acc[1][2 * jp + 1], af1, &bf[2]);
            }
        }
        __syncthreads();
    }

#pragma unroll
    for (int i = 0; i < 2; i++) {
        int r0 = m0 + wm * 32 + i * 16 + r;
        int r1 = r0 + 8;
#pragma unroll
        for (int j = 0; j < 8; j++) {
            int nb = n0 + wn * 64 + j * 8 + 2 * c;
            float b0 = bias[nb], b1 = bias[nb + 1];
            *(float2*)&out[(size_t)r0 * HID + nb] =
                make_float2(acc[i][j][0] + b0, acc[i][j][1] + b1);
            *(float2*)&out[(size_t)r1 * HID + nb] =
                make_float2(acc[i][j][2] + b0, acc[i][j][3] + b1);
        }
    }
}

// ---------------------------------------------------------------------------
// Tensor-core flash attention (causal, tf32, LDSM fragment loads).
// smem (floats): Qs 16384 | Ks 2x8192 | Vs 2x8192 | Ps 8192 = 224KB
// ---------------------------------------------------------------------------
#define QS_OFF 0
#define KS_OFF 16384
#define VS_OFF 32768
#define PS_OFF 49152
#define ATTN_SMEM_FLOATS 57344

__global__ __launch_bounds__(256, 1)
void attn_tc_kernel()
{
    extern __shared__ float sm[];
    float* Ps = sm + PS_OFF;

    const int t    = threadIdx.x;
    const int lane = t & 31;
    const int w    = t >> 5;
    const int r    = lane >> 2;
    const int c    = lane & 3;
    const int qbI  = 15 - blockIdx.x;
    const int bh   = blockIdx.y;
    const int q0   = qbI * 128;
    const int nkb  = 2 * qbI + 2;
    const float scale = 0.08838834764831845f; // 1/sqrt(128)

    const int lane7 = lane & 7;
    const int a_sel = (lane >> 4) & 1;
    const int a_i16 = ((lane >> 3) & 1) * 8;
    const int b_sel = (lane >> 3) & 1;
    const int b_n8  = ((lane >> 4) & 1) * 8;

    const float* Qg = g_Q  + (size_t)bh * SEQ * HDIM;
    const float* Kg = g_K  + (size_t)bh * SEQ * HDIM;
    const float* Vg = g_Vt + (size_t)bh * HDIM * SEQ;

    const uint32_t smu   = smem_u32(sm);
    const uint32_t Qs_u  = smu;                     // 512B rows
    const uint32_t Ps_u  = smu + PS_OFF * 4;        // 256B rows

    // ldmatrix row offsets (bytes)
    const int a_roQ = (w * 16 + a_i16 + lane7) * 512;
    const int a_roP = (w * 16 + a_i16 + lane7) * 256;
    int b_roK[4];
#pragma unroll
    for (int jp = 0; jp < 4; jp++)
        b_roK[jp] = (jp * 16 + b_n8 + lane7) * 512;
    int b_roV[8];
#pragma unroll
    for (int jp = 0; jp < 8; jp++)
        b_roV[jp] = (jp * 16 + b_n8 + lane7) * 256;

    auto issueKV = [&](int kb, int buf) {
        float* Ksb = sm + KS_OFF + buf * 8192;
        float* Vsb = sm + VS_OFF + buf * 8192;
        const int k0 = kb * 64;
#pragma unroll
        for (int i = 0; i < 8; i++) {
            int id = t + i * 256;
            int row = id >> 5, ck = id & 31;
            cp_async16(Ksb + row * 128 + swz(row & 7, ck) * 4,
                       Kg + (size_t)(k0 + row) * HDIM + ck * 4);
        }
#pragma unroll
        for (int i = 0; i < 8; i++) {
            int id = t + i * 256;
            int row = id >> 4, ck = id & 15;
            cp_async16(Vsb + row * 64 + swz(row & 7, ck) * 4,
                       Vg + (size_t)row * SEQ + k0 + ck * 4);
        }
        asm volatile("cp.async.commit_group;\n");
    };

#pragma unroll
    for (int i = 0; i < 16; i++) {
        int id = t + i * 256;
        int row = id >> 5, ck = id & 31;
        cp_async16(sm + row * 128 + swz(row & 7, ck) * 4,
                   Qg + (size_t)(q0 + row) * HDIM + ck * 4);
    }
    issueKV(0, 0);

    float m_s[2], l_s[2], O[16][4];
#pragma unroll
    for (int e = 0; e < 2; e++) { m_s[e] = -1e30f; l_s[e] = 0.f; }
#pragma unroll
    for (int j = 0; j < 16; j++)
#pragma unroll
        for (int e = 0; e < 4; e++) O[j][e] = 0.f;

    const int qrow = w * 16 + r;

    for (int kb = 0; kb < nkb; kb++) {
        const int buf = kb & 1;
        const int k0  = kb * 64;
        if (kb + 1 < nkb) {
            issueKV(kb + 1, (kb + 1) & 1);
            asm volatile("cp.async.wait_group 1;\n");
        } else {
            asm volatile("cp.async.wait_group 0;\n");
        }
        __syncthreads();

        const uint32_t Ks_u = smu + (KS_OFF + buf * 8192) * 4;
        const uint32_t Vs_u = smu + (VS_OFF + buf * 8192) * 4;

        // ---- S = Q K^T ----
        float sacc[8][4];
#pragma unroll
        for (int j = 0; j < 8; j++)
#pragma unroll
            for (int e = 0; e < 4; e++) sacc[j][e] = 0.f;

#pragma unroll
        for (int ks = 0; ks < 16; ks++) {
            const int cka = 2 * ks + a_sel;
            const int ckb = 2 * ks + b_sel;
            const int ea = swz(lane7, cka) << 4;
            const int eb = swz(lane7, ckb) << 4;
            uint32_t a[4];
            ldsm4(a, Qs_u + a_roQ + ea);
#pragma unroll
            for (int jp = 0; jp < 4; jp++) {
                uint32_t bf[4];
                ldsm4(bf, Ks_u + b_roK[jp] + eb);
                mma_tf32(sacc[2 * jp],     a, &bf[0]);
                mma_tf32(sacc[2 * jp + 1], a, &bf[2]);
            }
        }

        // ---- scale + causal mask ----
        const bool need_mask = (k0 + 63 > q0);
#pragma unroll
        for (int j = 0; j < 8; j++)
#pragma unroll
            for (int e = 0; e < 4; e++) {
                float v = sacc[j][e] * scale;
                if (need_mask) {
                    int col = k0 + j * 8 + 2 * c + (e & 1);
                    int row = q0 + qrow + ((e & 2) ? 8 : 0);
                    if (col > row) v = -1e30f;
                }
                sacc[j][e] = v;
            }

        // ---- online softmax ----
#pragma unroll
        for (int half = 0; half < 2; half++) {
            const int e0 = half * 2;
            float rmax = -1e30f;
#pragma unroll
            for (int j = 0; j < 8; j++)
                rmax = fmaxf(rmax, fmaxf(sacc[j][e0], sacc[j][e0 + 1]));
            rmax = fmaxf(rmax, __shfl_xor_sync(0xffffffffu, rmax, 1));
            rmax = fmaxf(rmax, __shfl_xor_sync(0xffffffffu, rmax, 2));
            float mnew = fmaxf(m_s[half], rmax);
            float corr = __expf(m_s[half] - mnew);
            float rsum = 0.f;
#pragma unroll
            for (int j = 0; j < 8; j++) {
                float p0 = __expf(sacc[j][e0] - mnew);
                float p1 = __expf(sacc[j][e0 + 1] - mnew);
                sacc[j][e0] = p0; sacc[j][e0 + 1] = p1;
                rsum += p0 + p1;
            }
            rsum += __shfl_xor_sync(0xffffffffu, rsum, 1);
            rsum += __shfl_xor_sync(0xffffffffu, rsum, 2);
            l_s[half] = l_s[half] * corr + rsum;
            m_s[half] = mnew;
#pragma unroll
            for (int j = 0; j < 16; j++) {
                O[j][e0]     *= corr;
                O[j][e0 + 1] *= corr;
            }
        }

        // ---- P -> smem (tf32-rounded) ----
#pragma unroll
        for (int j = 0; j < 8; j++) {
            int ck = 2 * j + (c >> 1);
            int off = swz(r, ck) * 4 + (c & 1) * 2;
            *(float2*)&Ps[qrow * 64 + off] =
                make_float2(rnd_tf32(sacc[j][0]), rnd_tf32(sacc[j][1]));
            *(float2*)&Ps[(qrow + 8) * 64 + off] =
                make_float2(rnd_tf32(sacc[j][2]), rnd_tf32(sacc[j][3]));
        }
        __syncwarp();

        // ---- O += P V ----
#pragma unroll
        for (int ks = 0; ks < 8; ks++) {
            const int cka = 2 * ks + a_sel;
            const int ckb = 2 * ks + b_sel;
            const int ea = swz(lane7, cka) << 4;
            const int eb = swz(lane7, ckb) << 4;
            uint32_t a[4];
            ldsm4(a, Ps_u + a_roP + ea);
#pragma unroll
            for (int jp = 0; jp < 8; jp++) {
                uint32_t bf[4];
                ldsm4(bf, Vs_u + b_roV[jp] + eb);
                mma_tf32(O[2 * jp],     a, &bf[0]);
                mma_tf32(O[2 * jp + 1], a, &bf[2]);
            }
        }
        __syncthreads();
    }

    const int b = bh >> 4, h = bh & 15;
    const float inv0 = 1.f / l_s[0];
    const float inv1 = 1.f / l_s[1];
    const int row0 = q0 + qrow, row1 = row0 + 8;
#pragma unroll
    for (int j = 0; j < 16; j++) {
        int n = h * HDIM + j * 8 + 2 * c;
        *(float2*)&g_attn[(size_t)(b * SEQ + row0) * HID + n] =
            make_float2(rnd_tf32(O[j][0] * inv0), rnd_tf32(O[j][1] * inv0));
        *(float2*)&g_attn[(size_t)(b * SEQ + row1) * HID + n] =
            make_float2(rnd_tf32(O[j][2] * inv1), rnd_tf32(O[j][3] * inv1));
    }
}

// ---------------------------------------------------------------------------
extern "C" void kernel_launch(void* const* d_in, const int* in_sizes, int n_in,
                              void* d_out, int out_size)
{
    const float* x  = (const float*)d_in[0];
    const float* Wq = (const float*)d_in[1];
    const float* bq = (const float*)d_in[2];
    const float* Wk = (const float*)d_in[3];
    const float* bk = (const float*)d_in[4];
    const float* Wv = (const float*)d_in[5];
    const float* bv = (const float*)d_in[6];
    const float* Wo = (const float*)d_in[7];
    const float* bo = (const float*)d_in[8];
    float* out = (float*)d_out;

    float *q, *k, *vt, *attn, *xr, *wr, *bcat;
    cudaGetSymbolAddress((void**)&q,    g_Q);
    cudaGetSymbolAddress((void**)&k,    g_K);
    cudaGetSymbolAddress((void**)&vt,   g_Vt);
    cudaGetSymbolAddress((void**)&attn, g_attn);
    cudaGetSymbolAddress((void**)&xr,   g_xr);
    cudaGetSymbolAddress((void**)&wr,   g_Wr);
    cudaGetSymbolAddress((void**)&bcat, g_bqkv);

    const size_t gemm_smem = BUF_FLOATS * 2 * sizeof(float);        // 64 KB
    cudaFuncSetAttribute(gemm_qkv_kernel,
                         cudaFuncAttributeMaxDynamicSharedMemorySize, (int)gemm_smem);
    cudaFuncSetAttribute(gemm_o_kernel,
                         cudaFuncAttributeMaxDynamicSharedMemorySize, (int)gemm_smem);
    const size_t attn_smem = ATTN_SMEM_FLOATS * sizeof(float);      // 224 KB
    cudaFuncSetAttribute(attn_tc_kernel,
                         cudaFuncAttributeMaxDynamicSharedMemorySize, (int)attn_smem);

    const int NX4 = MROWS * HID / 4;
    const int NW4 = HID * HID / 4;
    float* wo_r = wr + 3ull * HID * HID;

    round_tf32_kernel<<<NX4 / 256, 256>>>(x, xr, NX4);
    round_w4_kernel<<<4 * NW4 / 256, 256>>>(Wq, Wk, Wv, Wo, wr, NW4);
    concat_bias_kernel<<<3 * HID / 256, 256>>>(bq, bk, bv, bcat);

    gemm_qkv_kernel<<<dim3(3 * HID / 128, MROWS / 128), 256, gemm_smem>>>(
        xr, wr, q, k, vt);
    attn_tc_kernel<<<dim3(SEQ / 128, BH), 256, attn_smem>>>();
    gemm_o_kernel<<<dim3(HID / 128, MROWS / 128), 256, gemm_smem>>>(
        attn, wo_r, bo, out);
}